// round 14
// baseline (speedup 1.0000x reference)
#include <cuda_runtime.h>
#include <cuda_fp16.h>
#include <cstdint>
#include <cstddef>

// ---------------------------------------------------------------------------
// RNN_fish, persistent HMMA kernel, single fp16 chain:
//   h_t = 0.8*h_{t-1} + (g.h_{t-1}) @ (0.2*wrec^T) + U_t
// R13 (resubmit): hierarchical grid barrier (9 group counters x 16 CTAs +
// root) to kill same-address ATOMG serialization at the arrive. Rest = R12.
// ---------------------------------------------------------------------------

namespace {
constexpr int Bn = 64;
constexpr int Sn = 512;
constexpr int In = 128;
constexpr int Hn = 2048;
constexpr int On = 128;
constexpr int KSPLIT = 9;
constexpr int NCTA = 144;             // 16 j-tiles x 9 k-slices
constexpr int NTHR = 512;             // 16 warps (8 compute)
constexpr int HB = Hn * Bn;
constexpr int NGRP = 9;               // barrier groups of 16 CTAs
constexpr float kNoise = 0.005f;
constexpr float kAlpha = 0.2f;
constexpr float kLoInv = 1.0f / 4096.0f;

// k16-units per slice: slices 0,1 get 15, slices 2..8 get 14 (2*15+7*14=128)
__host__ __device__ __forceinline__ int slice_units(int kq) { return 14 + (kq < 2); }
__host__ __device__ __forceinline__ int slice_start16(int kq) {
    return kq * 14 + (kq < 2 ? kq : 2);
}

// loop smem layout (bytes). Rows padded to 528B -> conflict-free ldmatrix.
constexpr int ROWB = 528;
constexpr int OFF_WH = 0;                       // 128*528 = 67584
constexpr int OFF_BH = OFF_WH + 128 * ROWB;     // 67584 (+64*528 = 33792)
constexpr int OFF_STG = OFF_BH;                 // phase-2 stage overlays B
constexpr int SMEM_TOTAL = OFF_BH + 64 * ROWB;  // 101376

// u-kernel smem layout
constexpr int UROWB = 272;                      // 128 halves + 16B pad
constexpr int UOFF_BH = 64 * UROWB;             // A: 64 rows -> 17408
constexpr int UOFF_BL = UOFF_BH + 128 * UROWB;  // 52224
constexpr int USMEM = UOFF_BL + 128 * UROWB;    // 87040 (stage overlays A+Bhi)

// out-kernel smem layout
constexpr int ORB = 272;
constexpr int OFF_OB = 64 * ORB;
constexpr int OSMEM = OFF_OB + 128 * ORB;       // 52224
}

// device globals (allocation-free rule)
__device__ float g_U[(size_t)Sn * Hn * Bn];          // [t][j][b] (t>=1)
__device__ float g_part[(size_t)KSPLIT * Hn * Bn];   // [q][j][b]
__device__ __half g_Wh[(size_t)Hn * Hn];             // [j][k] fp16 of 0.2*g[k]*wrec[j][k]
__device__ __half g_hb[(size_t)Bn * Hn];             // [b][k] fp16 h_{t-1}
__device__ __half g_hist[(size_t)Sn * Bn * Hn];      // [t][b][k] fp16 h history
__device__ __half g_woT[(size_t)On * Hn];            // [o][k] fp16 wout^T
__device__ __half g_wiTh[(size_t)Hn * In];           // [j][i] fp16 hi of wi^T
__device__ __half g_wiTl[(size_t)Hn * In];           // [j][i] fp16 4096*lo
__device__ __half g_xh[(size_t)Bn * Sn * In];        // [b][t][i] fp16 x
__device__ unsigned g_grp[NGRP * 32];                // group arrive counters (128B apart)
__device__ unsigned g_root;                          // root arrive counter
__device__ unsigned g_bar_gen;                       // generation (spin target)

// ---- helpers ----
__device__ __forceinline__ uint32_t smem_u32(const void* p) {
    uint32_t a;
    asm("{ .reg .u64 t; cvta.to.shared.u64 t, %1; cvt.u32.u64 %0, t; }" : "=r"(a) : "l"(p));
    return a;
}
__device__ __forceinline__ void ldsm4(uint32_t a[4], uint32_t addr) {
    asm volatile("ldmatrix.sync.aligned.m8n8.x4.shared.b16 {%0,%1,%2,%3}, [%4];"
                 : "=r"(a[0]), "=r"(a[1]), "=r"(a[2]), "=r"(a[3]) : "r"(addr));
}
__device__ __forceinline__ void mma16816(float c[4], const uint32_t a[4],
                                         uint32_t b0, uint32_t b1) {
    asm volatile("mma.sync.aligned.m16n8k16.row.col.f32.f16.f16.f32 "
                 "{%0,%1,%2,%3}, {%4,%5,%6,%7}, {%8,%9}, {%0,%1,%2,%3};"
                 : "+f"(c[0]), "+f"(c[1]), "+f"(c[2]), "+f"(c[3])
                 : "r"(a[0]), "r"(a[1]), "r"(a[2]), "r"(a[3]), "r"(b0), "r"(b1));
}

// hierarchical grid barrier (replay-deterministic: counters ->0, gen monotone)
__device__ __forceinline__ void grid_sync_dev(int grp) {
    __syncthreads();
    if (threadIdx.x == 0) {
        __threadfence();
        unsigned old, my;
        asm volatile("ld.acquire.gpu.global.u32 %0, [%1];"
                     : "=r"(old) : "l"(&g_bar_gen) : "memory");
        asm volatile("atom.release.gpu.global.add.u32 %0, [%1], %2;"
                     : "=r"(my) : "l"(&g_grp[grp * 32]), "r"(1u) : "memory");
        if (my == 15u) {
            unsigned rmy;
            asm volatile("atom.release.gpu.global.add.u32 %0, [%1], %2;"
                         : "=r"(rmy) : "l"(&g_root), "r"(1u) : "memory");
            if (rmy == (unsigned)(NGRP - 1)) {
                // all groups full and all leaders at root: reset, then release
                #pragma unroll
                for (int i = 0; i < NGRP; i++)
                    asm volatile("st.global.u32 [%0], %1;"
                                 :: "l"(&g_grp[i * 32]), "r"(0u) : "memory");
                asm volatile("st.global.u32 [%0], %1;" :: "l"(&g_root), "r"(0u) : "memory");
                asm volatile("red.release.gpu.global.add.u32 [%0], %1;"
                             :: "l"(&g_bar_gen), "r"(1u) : "memory");
            } else {
                unsigned cur;
                do {
                    asm volatile("ld.acquire.gpu.global.u32 %0, [%1];"
                                 : "=r"(cur) : "l"(&g_bar_gen) : "memory");
                } while (cur == old);
            }
        } else {
            unsigned cur;
            do {
                asm volatile("ld.acquire.gpu.global.u32 %0, [%1];"
                             : "=r"(cur) : "l"(&g_bar_gen) : "memory");
            } while (cur == old);
        }
        __threadfence();
    }
    __syncthreads();
}

// ---------------------------------------------------------------------------
// prep kernels
// ---------------------------------------------------------------------------
__global__ void wprep_kernel(const float* __restrict__ wrec, const float* __restrict__ g) {
    int n = blockIdx.x * blockDim.x + threadIdx.x;      // < Hn*Hn  ([j][k])
    int k = n & (Hn - 1);
    g_Wh[n] = __float2half_rn(kAlpha * g[k] * wrec[n]);
}

__global__ void hbinit_kernel(const float* __restrict__ h0) {
    int n = blockIdx.x * blockDim.x + threadIdx.x;      // < Bn*Hn, [b][k]
    __half v = __float2half_rn(h0[n & (Hn - 1)]);
    g_hb[n] = v;
    g_hist[n] = v;                                      // t = 0 slice
}

__global__ void xhprep_kernel(const float* __restrict__ x) {
    int n = blockIdx.x * blockDim.x + threadIdx.x;      // < Bn*Sn*In
    g_xh[n] = __float2half_rn(x[n]);
}

__global__ __launch_bounds__(1024) void wtprep_kernel(const float* __restrict__ wout) {
    __shared__ float s[32][33];
    int tx = threadIdx.x, ty = threadIdx.y;
    int k0 = blockIdx.x * 32, o0 = blockIdx.y * 32;
    s[ty][tx] = wout[(size_t)(k0 + ty) * On + o0 + tx];
    __syncthreads();
    g_woT[(size_t)(o0 + ty) * Hn + k0 + tx] = __float2half_rn(s[tx][ty]);
}

__global__ __launch_bounds__(1024) void witprep_kernel(const float* __restrict__ wi) {
    __shared__ float s[32][33];
    int tx = threadIdx.x, ty = threadIdx.y;
    int i0 = blockIdx.x * 32, j0 = blockIdx.y * 32;
    s[ty][tx] = wi[(size_t)(i0 + ty) * Hn + j0 + tx];
    __syncthreads();
    float v = s[tx][ty];
    __half hi = __float2half_rn(v);
    g_wiTh[(size_t)(j0 + ty) * In + i0 + tx] = hi;
    g_wiTl[(size_t)(j0 + ty) * In + i0 + tx] =
        __float2half_rn((v - __half2float(hi)) * 4096.0f);
}

// ---------------------------------------------------------------------------
// u_kernel (HMMA): U[t][j][b] = alpha * x[b][t-1]@wi[:,j] + noise*n[b][t-1][j]
// ---------------------------------------------------------------------------
__global__ __launch_bounds__(256) void u_kernel(const float* __restrict__ noise) {
    extern __shared__ char sm[];
    const uint32_t sb = smem_u32(sm);
    const int jt = blockIdx.x, t = blockIdx.y + 1;
    const int j0 = jt * 128;
    const int tid = threadIdx.x;
    const int wid = tid >> 5, lane = tid & 31;
    const int mgb = wid >> 2;            // 0..1: 32 b each
    const int njw = wid & 3;             // 0..3: 32 j each
    const int g8 = lane >> 2, tg = lane & 3;

    #pragma unroll
    for (int p = 0; p < 4; p++) {
        int f = tid + p * 256;           // < 1024
        int r = f >> 4, c = f & 15;
        *(uint4*)(sm + r * UROWB + c * 16) =
            *(const uint4*)&g_xh[((size_t)r * Sn + (t - 1)) * In + c * 8];
    }
    #pragma unroll
    for (int p = 0; p < 8; p++) {
        int f = tid + p * 256;           // < 2048
        int r = f >> 4, c = f & 15;
        size_t gi = (size_t)(j0 + r) * In + c * 8;
        *(uint4*)(sm + UOFF_BH + r * UROWB + c * 16) = *(const uint4*)&g_wiTh[gi];
        *(uint4*)(sm + UOFF_BL + r * UROWB + c * 16) = *(const uint4*)&g_wiTl[gi];
    }
    __syncthreads();

    const uint32_t aLane =
        sb + (uint32_t)(mgb * 32 + (lane & 15)) * UROWB + (lane >> 4) * 16;
    const uint32_t bLane =
        (uint32_t)(njw * 32 + (lane & 7) + ((lane >> 4) & 1) * 8) * UROWB +
        ((lane >> 3) & 1) * 16;

    float a1[2][4][4] = {}, a2[2][4][4] = {};
    #pragma unroll
    for (int kk = 0; kk < 8; kk++) {
        uint32_t A0[4], A1[4], Bv[4], Bw[4];
        ldsm4(A0, aLane + kk * 32);
        ldsm4(A1, aLane + kk * 32 + 16 * UROWB);
        ldsm4(Bv, sb + UOFF_BH + bLane + kk * 32);
        ldsm4(Bw, sb + UOFF_BH + bLane + kk * 32 + 16 * UROWB);
        mma16816(a1[0][0], A0, Bv[0], Bv[1]); mma16816(a1[0][1], A0, Bv[2], Bv[3]);
        mma16816(a1[0][2], A0, Bw[0], Bw[1]); mma16816(a1[0][3], A0, Bw[2], Bw[3]);
        mma16816(a1[1][0], A1, Bv[0], Bv[1]); mma16816(a1[1][1], A1, Bv[2], Bv[3]);
        mma16816(a1[1][2], A1, Bw[0], Bw[1]); mma16816(a1[1][3], A1, Bw[2], Bw[3]);
        ldsm4(Bv, sb + UOFF_BL + bLane + kk * 32);
        ldsm4(Bw, sb + UOFF_BL + bLane + kk * 32 + 16 * UROWB);
        mma16816(a2[0][0], A0, Bv[0], Bv[1]); mma16816(a2[0][1], A0, Bv[2], Bv[3]);
        mma16816(a2[0][2], A0, Bw[0], Bw[1]); mma16816(a2[0][3], A0, Bw[2], Bw[3]);
        mma16816(a2[1][0], A1, Bv[0], Bv[1]); mma16816(a2[1][1], A1, Bv[2], Bv[3]);
        mma16816(a2[1][2], A1, Bw[0], Bw[1]); mma16816(a2[1][3], A1, Bw[2], Bw[3]);
    }
    __syncthreads();                     // done reading A/B; stage overlays them

    float (*stage)[132] = (float (*)[132])sm;   // [b 64][j 128]
    #pragma unroll
    for (int mt = 0; mt < 2; mt++)
        #pragma unroll
        for (int nt = 0; nt < 4; nt++) {
            int rb = mgb * 32 + mt * 16 + g8;
            int jc = njw * 32 + nt * 8 + tg * 2;
            stage[rb][jc]     = fmaf(kLoInv, a2[mt][nt][0], a1[mt][nt][0]);
            stage[rb][jc + 1] = fmaf(kLoInv, a2[mt][nt][1], a1[mt][nt][1]);
            stage[rb + 8][jc]     = fmaf(kLoInv, a2[mt][nt][2], a1[mt][nt][2]);
            stage[rb + 8][jc + 1] = fmaf(kLoInv, a2[mt][nt][3], a1[mt][nt][3]);
        }
    __syncthreads();

    #pragma unroll
    for (int rep = 0; rep < 8; rep++) {
        int b = wid * 8 + rep;
        #pragma unroll
        for (int c = 0; c < 4; c++) {
            int j = c * 32 + lane;
            float nv = noise[((size_t)b * Sn + (t - 1)) * Hn + j0 + j];
            stage[b][j] = fmaf(kAlpha, stage[b][j], kNoise * nv);
        }
    }
    __syncthreads();

    {
        int j = tid >> 1, bh = (tid & 1) * 32;
        #pragma unroll
        for (int bc = 0; bc < 8; bc++) {
            int b0 = bh + bc * 4;
            float4 v = make_float4(stage[b0][j], stage[b0 + 1][j],
                                   stage[b0 + 2][j], stage[b0 + 3][j]);
            *(float4*)&g_U[((size_t)t * Hn + j0 + j) * Bn + b0] = v;
        }
    }
}

// ---------------------------------------------------------------------------
// persistent HMMA loop. CTA (jt,kq): partial D[128j x 64b] over its k-slice.
// 8 compute warps: mg = wid>>1 (4 x 32j), nh = wid&1 (2 x 32b); each warp
// full k-slice. Warps 8-15: loads + phase-2 only. Barrier = hierarchical.
// ---------------------------------------------------------------------------
__global__ __launch_bounds__(NTHR, 1) void loop_kernel(const float* __restrict__ h0) {
    extern __shared__ char smem[];
    const uint32_t sb = smem_u32(smem);
    const int tid = threadIdx.x;
    const int wid = tid >> 5, lane = tid & 31;
    const int cta = blockIdx.x;
    const int jt = cta / KSPLIT, kq = cta % KSPLIT;
    const int grp = cta >> 4;                 // barrier group (0..8)
    const int j0 = jt * 128;
    const int ku = slice_units(kq);           // 14 or 15
    const int ku2 = ku * 2;                   // 16B chunks per row
    const int kbase = slice_start16(kq) * 16; // element base
    const int rc = cta * 16;                  // phase-2 j-base (cta < 128 only)

    const int mg = wid >> 1;                  // 0..3 (32 j each, compute warps)
    const int nh = wid & 1;                   // 0..1 (32 b each)
    const int g8 = lane >> 2, tg = lane & 3;

    // phase-2 ownership (fixed forever): j = rc + jl, b = bb..bb+1
    const int jl = (tid * 2) >> 6;            // 0..15
    const int bb = (tid * 2) & 63;
    const size_t ownIdx = (size_t)(rc + jl) * Bn + bb;
    float2 hreg = make_float2(0.f, 0.f);
    if (cta < 128) { float v = h0[rc + jl]; hreg = make_float2(v, v); }

    // ---- prologue: resident W -> SMEM (padded rows) ----
    for (int p = 0; p < 8; p++) {
        int f = tid + p * 512;                // < 4096
        int r = f >> 5, c = f & 31;
        if (c < ku2)
            *(uint4*)(smem + OFF_WH + r * ROWB + c * 16) =
                *(const uint4*)&g_Wh[(size_t)(j0 + r) * Hn + kbase + c * 8];
    }
    __syncthreads();

    const uint32_t aLane =
        sb + OFF_WH + (uint32_t)(mg * 32 + (lane & 15)) * ROWB + (lane >> 4) * 16;
    const uint32_t bLane =
        sb + OFF_BH + (uint32_t)(nh * 32 + (lane & 7) + ((lane >> 4) & 1) * 8) * ROWB +
        ((lane >> 3) & 1) * 16;
    float (*stage)[66] = (float (*)[66])(smem + OFF_STG);

    for (int t = 1; t < Sn; t++) {
        // ---- load B (fp16 h slice) ----
        #pragma unroll
        for (int p = 0; p < 4; p++) {
            int f = tid + p * 512;            // < 2048
            int b = f >> 5, c = f & 31;
            if (c < ku2)
                *(uint4*)(smem + OFF_BH + b * ROWB + c * 16) =
                    __ldcg((const uint4*)&g_hb[(size_t)b * Hn + kbase + c * 8]);
        }
        __syncthreads();

        // ---- single mma chain, full k-slice per compute warp ----
        float acc[2][4][4] = {};
        if (wid < 8) {
            #pragma unroll 5
            for (int kk = 0; kk < ku; kk++) {
                uint32_t A0[4], A1[4], Bv[4], Bw[4];
                ldsm4(A0, aLane + kk * 32);
                ldsm4(A1, aLane + kk * 32 + 16 * ROWB);
                ldsm4(Bv, bLane + kk * 32);
                ldsm4(Bw, bLane + kk * 32 + 16 * ROWB);
                mma16816(acc[0][0], A0, Bv[0], Bv[1]);
                mma16816(acc[0][1], A0, Bv[2], Bv[3]);
                mma16816(acc[0][2], A0, Bw[0], Bw[1]);
                mma16816(acc[0][3], A0, Bw[2], Bw[3]);
                mma16816(acc[1][0], A1, Bv[0], Bv[1]);
                mma16816(acc[1][1], A1, Bv[2], Bv[3]);
                mma16816(acc[1][2], A1, Bw[0], Bw[1]);
                mma16816(acc[1][3], A1, Bw[2], Bw[3]);
            }
        }
        __syncthreads();                      // done reading B (stage overlays)

        // ---- direct store to g_part (disjoint per compute warp) ----
        if (wid < 8) {
            #pragma unroll
            for (int mt = 0; mt < 2; mt++)
                #pragma unroll
                for (int nt = 0; nt < 4; nt++) {
                    int r0 = mt * 16 + g8, cc = nt * 8 + tg * 2;
                    int j = j0 + mg * 32 + r0;
                    int bc = nh * 32 + cc;
                    __stcg((float2*)&g_part[((size_t)kq * Hn + j) * Bn + bc],
                           make_float2(acc[mt][nt][0], acc[mt][nt][1]));
                    __stcg((float2*)&g_part[((size_t)kq * Hn + j + 8) * Bn + bc],
                           make_float2(acc[mt][nt][2], acc[mt][nt][3]));
                }
        }

        // ---- prefetch phase-2 U (barrier-independent) ----
        float2 uu = make_float2(0.f, 0.f);
        if (cta < 128) uu = *(const float2*)&g_U[(size_t)t * HB + ownIdx];

        grid_sync_dev(grp);

        // ---- phase 2: reduce 9 k-slices + leak + U; CTAs 0..127 own 16 j each ----
        if (cta < 128) {
            float2 s = make_float2(0.f, 0.f);
            #pragma unroll
            for (int q = 0; q < KSPLIT; q++) {
                float2 v = __ldcg((const float2*)&g_part[(size_t)q * HB + ownIdx]);
                s.x += v.x; s.y += v.y;
            }
            hreg = make_float2((1.f - kAlpha) * hreg.x + s.x + uu.x,
                               (1.f - kAlpha) * hreg.y + s.y + uu.y);
            *(float2*)&stage[jl][bb] = hreg;
            __syncthreads();
            int b = tid >> 3, kk = tid & 7;
            __half2 hv;
            hv.x = __float2half_rn(stage[kk * 2][b]);
            hv.y = __float2half_rn(stage[kk * 2 + 1][b]);
            size_t off = (size_t)b * Hn + rc + kk * 2;
            *(__half2*)&g_hb[off] = hv;
            *(__half2*)&g_hist[(size_t)t * HB + off] = hv;
        }

        grid_sync_dev(grp);
    }
}

// ---------------------------------------------------------------------------
// out[b][t][o] = sum_k g_hist[t][b][k] * woT[o][k]   (fp16 HMMA, one CTA per t)
// ---------------------------------------------------------------------------
__global__ __launch_bounds__(256) void out_kernel(float* __restrict__ out) {
    extern __shared__ char sm[];
    const uint32_t sb = smem_u32(sm);
    const int t = blockIdx.x, tid = threadIdx.x;
    const int wid = tid >> 5, lane = tid & 31;
    const int mg = wid >> 2, nh = wid & 3;

    const uint32_t aLane = (uint32_t)(mg * 32 + (lane & 15)) * ORB + (lane >> 4) * 16;
    const uint32_t bLane =
        (uint32_t)(nh * 32 + (lane & 7) + ((lane >> 4) & 1) * 8) * ORB +
        ((lane >> 3) & 1) * 16;
    const int g8 = lane >> 2, tg = lane & 3;

    float acc[2][4][4] = {};
    const __half* hsrc = g_hist + (size_t)t * HB;

    for (int k0 = 0; k0 < Hn; k0 += 128) {
        #pragma unroll
        for (int p = 0; p < 4; p++) {
            int f = tid + p * 256;
            int r = f >> 4, c = f & 15;
            *(uint4*)(sm + r * ORB + c * 16) =
                *(const uint4*)&hsrc[(size_t)r * Hn + k0 + c * 8];
        }
        #pragma unroll
        for (int p = 0; p < 8; p++) {
            int f = tid + p * 256;
            int r = f >> 4, c = f & 15;
            *(uint4*)(sm + OFF_OB + r * ORB + c * 16) =
                *(const uint4*)&g_woT[(size_t)r * Hn + k0 + c * 8];
        }
        __syncthreads();
        const uint32_t aB = sb + aLane, bB = sb + OFF_OB + bLane;
        #pragma unroll
        for (int kk = 0; kk < 8; kk++) {
            uint32_t A0[4], A1[4], Bv[4], Bw[4];
            ldsm4(A0, aB + kk * 32);
            ldsm4(A1, aB + kk * 32 + 16 * ORB);
            ldsm4(Bv, bB + kk * 32);
            ldsm4(Bw, bB + kk * 32 + 16 * ORB);
            mma16816(acc[0][0], A0, Bv[0], Bv[1]);
            mma16816(acc[0][1], A0, Bv[2], Bv[3]);
            mma16816(acc[0][2], A0, Bw[0], Bw[1]);
            mma16816(acc[0][3], A0, Bw[2], Bw[3]);
            mma16816(acc[1][0], A1, Bv[0], Bv[1]);
            mma16816(acc[1][1], A1, Bv[2], Bv[3]);
            mma16816(acc[1][2], A1, Bw[0], Bw[1]);
            mma16816(acc[1][3], A1, Bw[2], Bw[3]);
        }
        __syncthreads();
    }

    #pragma unroll
    for (int mt = 0; mt < 2; mt++)
        #pragma unroll
        for (int nt = 0; nt < 4; nt++) {
            int r0 = mt * 16 + g8, cc = nt * 8 + tg * 2;
            int b = mg * 32 + r0;
            int o = nh * 32 + cc;
            *(float2*)&out[((size_t)b * Sn + t) * On + o] =
                make_float2(acc[mt][nt][0], acc[mt][nt][1]);
            *(float2*)&out[((size_t)(b + 8) * Sn + t) * On + o] =
                make_float2(acc[mt][nt][2], acc[mt][nt][3]);
        }
}

// ---------------------------------------------------------------------------
extern "C" void kernel_launch(void* const* d_in, const int* in_sizes, int n_in,
                              void* d_out, int out_size) {
    const float* x     = (const float*)d_in[0];
    const float* noise = (const float*)d_in[1];
    const float* wi    = (const float*)d_in[2];
    const float* wrec  = (const float*)d_in[3];
    const float* wout  = (const float*)d_in[4];
    const float* g     = (const float*)d_in[5];
    const float* h0    = (const float*)d_in[6];
    float* out = (float*)d_out;

    cudaFuncSetAttribute(loop_kernel, cudaFuncAttributeMaxDynamicSharedMemorySize,
                         SMEM_TOTAL);
    cudaFuncSetAttribute(u_kernel, cudaFuncAttributeMaxDynamicSharedMemorySize,
                         USMEM);
    cudaFuncSetAttribute(out_kernel, cudaFuncAttributeMaxDynamicSharedMemorySize,
                         OSMEM);

    wprep_kernel<<<Hn * Hn / 256, 256>>>(wrec, g);
    wtprep_kernel<<<dim3(Hn / 32, On / 32), dim3(32, 32)>>>(wout);
    witprep_kernel<<<dim3(In / 32, Hn / 32), dim3(32, 32)>>>(wi);
    xhprep_kernel<<<Bn * Sn * In / 256, 256>>>(x);
    hbinit_kernel<<<HB / 256, 256>>>(h0);
    u_kernel<<<dim3(Hn / 128, Sn - 1), 256, USMEM>>>(noise);
    loop_kernel<<<NCTA, NTHR, SMEM_TOTAL>>>(h0);
    out_kernel<<<Sn, 256, OSMEM>>>(out);
}

// round 15
// speedup vs baseline: 1.4545x; 1.4545x over previous
#include <cuda_runtime.h>
#include <cuda_fp16.h>
#include <cstdint>
#include <cstddef>

// ---------------------------------------------------------------------------
// RNN_fish, R15: step-doubled persistent HMMA kernel.
//   M = 0.8I + 0.2*diag-free form; h_t = M h_{t-1} + U_t
//   h_{2i} = M^2 h_{2i-2} + V_i,  V_i = M U_{2i-1} + U_{2i}   (V precomputed)
//   h_{2i+1} = M h_{2i} + U_{2i+1}                            (post, parallel)
// Sequential loop: 255 steps (was 511). Flat grid barrier (R12, proven).
// ---------------------------------------------------------------------------

namespace {
constexpr int Bn = 64;
constexpr int Sn = 512;
constexpr int In = 128;
constexpr int Hn = 2048;
constexpr int On = 128;
constexpr int KSPLIT = 9;
constexpr int NCTA = 144;             // 16 j-tiles x 9 k-slices
constexpr int NTHR = 512;
constexpr int HB = Hn * Bn;
constexpr float kNoise = 0.005f;
constexpr float kAlpha = 0.2f;
constexpr float kLoInv = 1.0f / 4096.0f;

__host__ __device__ __forceinline__ int slice_units(int kq) { return 14 + (kq < 2); }
__host__ __device__ __forceinline__ int slice_start16(int kq) {
    return kq * 14 + (kq < 2 ? kq : 2);
}

// loop smem
constexpr int ROWB = 528;
constexpr int OFF_WH = 0;                       // 128*528
constexpr int OFF_BH = OFF_WH + 128 * ROWB;
constexpr int OFF_STG = OFF_BH;
constexpr int SMEM_TOTAL = OFF_BH + 64 * ROWB;  // 101376

// 128-wide GEMM kernels smem (mm2 / v / odd / u / out)
constexpr int GRB = 272;                        // 128 halves + pad
constexpr int GA = 128 * GRB;                   // 34816
// mm2: Ah,Al,Bh,Bl
constexpr int MM2_SMEM = 4 * GA;                // 139264
// v/odd: Ah,B (+ odd stage overlays)
constexpr int VO_SMEM = 2 * GA;                 // 69632
// u-kernel
constexpr int UOFF_BH = 64 * GRB;
constexpr int UOFF_BL = UOFF_BH + 128 * GRB;
constexpr int USMEM = UOFF_BL + 128 * GRB;      // 87040
// out-kernel
constexpr int OFF_OB = 64 * GRB;
constexpr int OSMEM = OFF_OB + 128 * GRB;       // 52224
}

// device globals
__device__ float g_U[(size_t)Sn * Hn * Bn];          // [t][j][b] fp32 (t>=1)
__device__ float g_V[(size_t)255 * Hn * Bn];         // [i][j][b] fp32
__device__ float g_part[(size_t)KSPLIT * Hn * Bn];   // [q][j][b]
__device__ __half g_Mh[(size_t)Hn * Hn];             // [j][k] fp16 hi of M
__device__ __half g_Ml[(size_t)Hn * Hn];             // [j][k] 4096*lo
__device__ __half g_MTh[(size_t)Hn * Hn];            // [k][j] transposed hi
__device__ __half g_MTl[(size_t)Hn * Hn];            // [k][j] transposed lo
__device__ __half g_M2[(size_t)Hn * Hn];             // [j][k] fp16 M^2
__device__ __half g_hist[(size_t)Sn * Bn * Hn];      // [t][b][k] fp16 h
__device__ __half g_Uo[(size_t)256 * Bn * Hn];       // [(t-1)/2][b][k] fp16, odd t
__device__ __half g_woT[(size_t)On * Hn];            // [o][k]
__device__ __half g_wiTh[(size_t)Hn * In];
__device__ __half g_wiTl[(size_t)Hn * In];
__device__ __half g_xh[(size_t)Bn * Sn * In];        // [b][t][i]
__device__ unsigned g_bar_count;
__device__ unsigned g_bar_gen;

// ---- helpers ----
__device__ __forceinline__ uint32_t smem_u32(const void* p) {
    uint32_t a;
    asm("{ .reg .u64 t; cvta.to.shared.u64 t, %1; cvt.u32.u64 %0, t; }" : "=r"(a) : "l"(p));
    return a;
}
__device__ __forceinline__ void ldsm4(uint32_t a[4], uint32_t addr) {
    asm volatile("ldmatrix.sync.aligned.m8n8.x4.shared.b16 {%0,%1,%2,%3}, [%4];"
                 : "=r"(a[0]), "=r"(a[1]), "=r"(a[2]), "=r"(a[3]) : "r"(addr));
}
__device__ __forceinline__ void mma16816(float c[4], const uint32_t a[4],
                                         uint32_t b0, uint32_t b1) {
    asm volatile("mma.sync.aligned.m16n8k16.row.col.f32.f16.f16.f32 "
                 "{%0,%1,%2,%3}, {%4,%5,%6,%7}, {%8,%9}, {%0,%1,%2,%3};"
                 : "+f"(c[0]), "+f"(c[1]), "+f"(c[2]), "+f"(c[3])
                 : "r"(a[0]), "r"(a[1]), "r"(a[2]), "r"(a[3]), "r"(b0), "r"(b1));
}

// flat grid barrier (R12, proven)
__device__ __forceinline__ void grid_sync_dev() {
    __syncthreads();
    if (threadIdx.x == 0) {
        __threadfence();
        unsigned old, my;
        asm volatile("ld.acquire.gpu.global.u32 %0, [%1];"
                     : "=r"(old) : "l"(&g_bar_gen) : "memory");
        asm volatile("atom.release.gpu.global.add.u32 %0, [%1], %2;"
                     : "=r"(my) : "l"(&g_bar_count), "r"(1u) : "memory");
        if (my == (unsigned)(NCTA - 1)) {
            asm volatile("st.global.u32 [%0], %1;" :: "l"(&g_bar_count), "r"(0u) : "memory");
            asm volatile("red.release.gpu.global.add.u32 [%0], %1;"
                         :: "l"(&g_bar_gen), "r"(1u) : "memory");
        } else {
            unsigned cur;
            do {
                asm volatile("ld.acquire.gpu.global.u32 %0, [%1];"
                             : "=r"(cur) : "l"(&g_bar_gen) : "memory");
            } while (cur == old);
        }
        __threadfence();
    }
    __syncthreads();
}

// ---------------------------------------------------------------------------
// prep kernels
// ---------------------------------------------------------------------------
// M = 0.8I + alpha*g[k]*wrec[j][k]; hi/lo both orientations
__global__ __launch_bounds__(1024) void mprep_kernel(const float* __restrict__ wrec,
                                                     const float* __restrict__ g) {
    __shared__ float sh[32][33], sl[32][33];
    int tx = threadIdx.x, ty = threadIdx.y;
    int j0 = blockIdx.y * 32, k0 = blockIdx.x * 32;
    int j = j0 + ty, k = k0 + tx;
    float v = kAlpha * g[k] * wrec[(size_t)j * Hn + k];
    if (j == k) v += 1.0f - kAlpha;
    __half hi = __float2half_rn(v);
    float lo = (v - __half2float(hi)) * 4096.0f;
    g_Mh[(size_t)j * Hn + k] = hi;
    g_Ml[(size_t)j * Hn + k] = __float2half_rn(lo);
    sh[ty][tx] = __half2float(hi);
    sl[ty][tx] = lo;
    __syncthreads();
    // transposed: row = k0+ty, col = j0+tx
    g_MTh[(size_t)(k0 + ty) * Hn + j0 + tx] = __float2half_rn(sh[tx][ty]);
    g_MTl[(size_t)(k0 + ty) * Hn + j0 + tx] = __float2half_rn(sl[tx][ty]);
}

__global__ void hbinit_kernel(const float* __restrict__ h0) {
    int n = blockIdx.x * blockDim.x + threadIdx.x;      // < Bn*Hn, [b][k]
    g_hist[n] = __float2half_rn(h0[n & (Hn - 1)]);      // t = 0
}

__global__ void xhprep_kernel(const float* __restrict__ x) {
    int n = blockIdx.x * blockDim.x + threadIdx.x;
    g_xh[n] = __float2half_rn(x[n]);
}

__global__ __launch_bounds__(1024) void wtprep_kernel(const float* __restrict__ wout) {
    __shared__ float s[32][33];
    int tx = threadIdx.x, ty = threadIdx.y;
    int k0 = blockIdx.x * 32, o0 = blockIdx.y * 32;
    s[ty][tx] = wout[(size_t)(k0 + ty) * On + o0 + tx];
    __syncthreads();
    g_woT[(size_t)(o0 + ty) * Hn + k0 + tx] = __float2half_rn(s[tx][ty]);
}

__global__ __launch_bounds__(1024) void witprep_kernel(const float* __restrict__ wi) {
    __shared__ float s[32][33];
    int tx = threadIdx.x, ty = threadIdx.y;
    int i0 = blockIdx.x * 32, j0 = blockIdx.y * 32;
    s[ty][tx] = wi[(size_t)(i0 + ty) * Hn + j0 + tx];
    __syncthreads();
    float v = s[tx][ty];
    __half hi = __float2half_rn(v);
    g_wiTh[(size_t)(j0 + ty) * In + i0 + tx] = hi;
    g_wiTl[(size_t)(j0 + ty) * In + i0 + tx] =
        __float2half_rn((v - __half2float(hi)) * 4096.0f);
}

// ---------------------------------------------------------------------------
// u_kernel: U[t][j][b] fp32; odd t additionally as fp16 [b][k] in g_Uo
// ---------------------------------------------------------------------------
__global__ __launch_bounds__(256) void u_kernel(const float* __restrict__ noise) {
    extern __shared__ char sm[];
    const uint32_t sb = smem_u32(sm);
    const int jt = blockIdx.x, t = blockIdx.y + 1;
    const int j0 = jt * 128;
    const int tid = threadIdx.x;
    const int wid = tid >> 5, lane = tid & 31;
    const int mgb = wid >> 2, njw = wid & 3;
    const int g8 = lane >> 2, tg = lane & 3;

    #pragma unroll
    for (int p = 0; p < 4; p++) {
        int f = tid + p * 256;
        int r = f >> 4, c = f & 15;
        *(uint4*)(sm + r * GRB + c * 16) =
            *(const uint4*)&g_xh[((size_t)r * Sn + (t - 1)) * In + c * 8];
    }
    #pragma unroll
    for (int p = 0; p < 8; p++) {
        int f = tid + p * 256;
        int r = f >> 4, c = f & 15;
        size_t gi = (size_t)(j0 + r) * In + c * 8;
        *(uint4*)(sm + UOFF_BH + r * GRB + c * 16) = *(const uint4*)&g_wiTh[gi];
        *(uint4*)(sm + UOFF_BL + r * GRB + c * 16) = *(const uint4*)&g_wiTl[gi];
    }
    __syncthreads();

    const uint32_t aLane =
        sb + (uint32_t)(mgb * 32 + (lane & 15)) * GRB + (lane >> 4) * 16;
    const uint32_t bLane =
        (uint32_t)(njw * 32 + (lane & 7) + ((lane >> 4) & 1) * 8) * GRB +
        ((lane >> 3) & 1) * 16;

    float a1[2][4][4] = {}, a2[2][4][4] = {};
    #pragma unroll
    for (int kk = 0; kk < 8; kk++) {
        uint32_t A0[4], A1[4], Bv[4], Bw[4];
        ldsm4(A0, aLane + kk * 32);
        ldsm4(A1, aLane + kk * 32 + 16 * GRB);
        ldsm4(Bv, sb + UOFF_BH + bLane + kk * 32);
        ldsm4(Bw, sb + UOFF_BH + bLane + kk * 32 + 16 * GRB);
        mma16816(a1[0][0], A0, Bv[0], Bv[1]); mma16816(a1[0][1], A0, Bv[2], Bv[3]);
        mma16816(a1[0][2], A0, Bw[0], Bw[1]); mma16816(a1[0][3], A0, Bw[2], Bw[3]);
        mma16816(a1[1][0], A1, Bv[0], Bv[1]); mma16816(a1[1][1], A1, Bv[2], Bv[3]);
        mma16816(a1[1][2], A1, Bw[0], Bw[1]); mma16816(a1[1][3], A1, Bw[2], Bw[3]);
        ldsm4(Bv, sb + UOFF_BL + bLane + kk * 32);
        ldsm4(Bw, sb + UOFF_BL + bLane + kk * 32 + 16 * GRB);
        mma16816(a2[0][0], A0, Bv[0], Bv[1]); mma16816(a2[0][1], A0, Bv[2], Bv[3]);
        mma16816(a2[0][2], A0, Bw[0], Bw[1]); mma16816(a2[0][3], A0, Bw[2], Bw[3]);
        mma16816(a2[1][0], A1, Bv[0], Bv[1]); mma16816(a2[1][1], A1, Bv[2], Bv[3]);
        mma16816(a2[1][2], A1, Bw[0], Bw[1]); mma16816(a2[1][3], A1, Bw[2], Bw[3]);
    }
    __syncthreads();

    float (*stage)[132] = (float (*)[132])sm;   // [b 64][j 128]
    #pragma unroll
    for (int mt = 0; mt < 2; mt++)
        #pragma unroll
        for (int nt = 0; nt < 4; nt++) {
            int rb = mgb * 32 + mt * 16 + g8;
            int jc = njw * 32 + nt * 8 + tg * 2;
            stage[rb][jc]     = fmaf(kLoInv, a2[mt][nt][0], a1[mt][nt][0]);
            stage[rb][jc + 1] = fmaf(kLoInv, a2[mt][nt][1], a1[mt][nt][1]);
            stage[rb + 8][jc]     = fmaf(kLoInv, a2[mt][nt][2], a1[mt][nt][2]);
            stage[rb + 8][jc + 1] = fmaf(kLoInv, a2[mt][nt][3], a1[mt][nt][3]);
        }
    __syncthreads();

    #pragma unroll
    for (int rep = 0; rep < 8; rep++) {
        int b = wid * 8 + rep;
        #pragma unroll
        for (int c = 0; c < 4; c++) {
            int j = c * 32 + lane;
            float nv = noise[((size_t)b * Sn + (t - 1)) * Hn + j0 + j];
            stage[b][j] = fmaf(kAlpha, stage[b][j], kNoise * nv);
        }
    }
    __syncthreads();

    {   // fp32 [j][b] store
        int j = tid >> 1, bh = (tid & 1) * 32;
        #pragma unroll
        for (int bc = 0; bc < 8; bc++) {
            int b0 = bh + bc * 4;
            float4 v = make_float4(stage[b0][j], stage[b0 + 1][j],
                                   stage[b0 + 2][j], stage[b0 + 3][j]);
            *(float4*)&g_U[((size_t)t * Hn + j0 + j) * Bn + b0] = v;
        }
    }
    if (t & 1) {   // fp16 [b][k] store for odd t
        int ui = (t - 1) >> 1;
        int b = tid >> 2;
        #pragma unroll
        for (int p = 0; p < 16; p++) {
            int jj = (tid & 3) * 2 + p * 8;
            __half2 hv;
            hv.x = __float2half_rn(stage[b][jj]);
            hv.y = __float2half_rn(stage[b][jj + 1]);
            *(__half2*)&g_Uo[(size_t)ui * HB + (size_t)b * Hn + j0 + jj] = hv;
        }
    }
}

// ---------------------------------------------------------------------------
// mm2_kernel: M2[j][k] = sum_m M[j][m]*M[m][k], 3 chains (hh + (hl+lh)/4096)
// CTA: 128j x 128k; grid (16,16); K=2048 in 128-chunks; 16 warps (4x4).
// ---------------------------------------------------------------------------
__global__ __launch_bounds__(512) void mm2_kernel() {
    extern __shared__ char sm[];
    const uint32_t sb = smem_u32(sm);
    const int j0 = blockIdx.x * 128, k0 = blockIdx.y * 128;
    const int tid = threadIdx.x;
    const int wid = tid >> 5, lane = tid & 31;
    const int mg = wid >> 2, nh = wid & 3;
    const int g8 = lane >> 2, tg = lane & 3;

    const uint32_t aOff = (uint32_t)(mg * 32 + (lane & 15)) * GRB + (lane >> 4) * 16;
    const uint32_t bOff =
        (uint32_t)(nh * 32 + (lane & 7) + ((lane >> 4) & 1) * 8) * GRB +
        ((lane >> 3) & 1) * 16;

    float a1[2][4][4] = {}, a2[2][4][4] = {};
    for (int m0 = 0; m0 < Hn; m0 += 128) {
        #pragma unroll
        for (int p = 0; p < 4; p++) {
            int f = tid + p * 512;            // < 2048
            int r = f >> 4, c = f & 15;
            size_t ga = (size_t)(j0 + r) * Hn + m0 + c * 8;
            size_t gb = (size_t)(k0 + r) * Hn + m0 + c * 8;
            *(uint4*)(sm + 0 * GA + r * GRB + c * 16) = *(const uint4*)&g_Mh[ga];
            *(uint4*)(sm + 1 * GA + r * GRB + c * 16) = *(const uint4*)&g_Ml[ga];
            *(uint4*)(sm + 2 * GA + r * GRB + c * 16) = *(const uint4*)&g_MTh[gb];
            *(uint4*)(sm + 3 * GA + r * GRB + c * 16) = *(const uint4*)&g_MTl[gb];
        }
        __syncthreads();
        #pragma unroll
        for (int kk = 0; kk < 8; kk++) {
            uint32_t Ah0[4], Ah1[4], Al0[4], Al1[4], Bh0[4], Bh1[4], Bl0[4], Bl1[4];
            ldsm4(Ah0, sb + 0 * GA + aOff + kk * 32);
            ldsm4(Ah1, sb + 0 * GA + aOff + kk * 32 + 16 * GRB);
            ldsm4(Al0, sb + 1 * GA + aOff + kk * 32);
            ldsm4(Al1, sb + 1 * GA + aOff + kk * 32 + 16 * GRB);
            ldsm4(Bh0, sb + 2 * GA + bOff + kk * 32);
            ldsm4(Bh1, sb + 2 * GA + bOff + kk * 32 + 16 * GRB);
            ldsm4(Bl0, sb + 3 * GA + bOff + kk * 32);
            ldsm4(Bl1, sb + 3 * GA + bOff + kk * 32 + 16 * GRB);
            // hh -> a1
            mma16816(a1[0][0], Ah0, Bh0[0], Bh0[1]); mma16816(a1[0][1], Ah0, Bh0[2], Bh0[3]);
            mma16816(a1[0][2], Ah0, Bh1[0], Bh1[1]); mma16816(a1[0][3], Ah0, Bh1[2], Bh1[3]);
            mma16816(a1[1][0], Ah1, Bh0[0], Bh0[1]); mma16816(a1[1][1], Ah1, Bh0[2], Bh0[3]);
            mma16816(a1[1][2], Ah1, Bh1[0], Bh1[1]); mma16816(a1[1][3], Ah1, Bh1[2], Bh1[3]);
            // hl -> a2
            mma16816(a2[0][0], Ah0, Bl0[0], Bl0[1]); mma16816(a2[0][1], Ah0, Bl0[2], Bl0[3]);
            mma16816(a2[0][2], Ah0, Bl1[0], Bl1[1]); mma16816(a2[0][3], Ah0, Bl1[2], Bl1[3]);
            mma16816(a2[1][0], Ah1, Bl0[0], Bl0[1]); mma16816(a2[1][1], Ah1, Bl0[2], Bl0[3]);
            mma16816(a2[1][2], Ah1, Bl1[0], Bl1[1]); mma16816(a2[1][3], Ah1, Bl1[2], Bl1[3]);
            // lh -> a2
            mma16816(a2[0][0], Al0, Bh0[0], Bh0[1]); mma16816(a2[0][1], Al0, Bh0[2], Bh0[3]);
            mma16816(a2[0][2], Al0, Bh1[0], Bh1[1]); mma16816(a2[0][3], Al0, Bh1[2], Bh1[3]);
            mma16816(a2[1][0], Al1, Bh0[0], Bh0[1]); mma16816(a2[1][1], Al1, Bh0[2], Bh0[3]);
            mma16816(a2[1][2], Al1, Bh1[0], Bh1[1]); mma16816(a2[1][3], Al1, Bh1[2], Bh1[3]);
        }
        __syncthreads();
    }
    #pragma unroll
    for (int mt = 0; mt < 2; mt++)
        #pragma unroll
        for (int nt = 0; nt < 4; nt++) {
            int j = j0 + mg * 32 + mt * 16 + g8;
            int k = k0 + nh * 32 + nt * 8 + tg * 2;
            __half2 v0, v1;
            v0.x = __float2half_rn(fmaf(kLoInv, a2[mt][nt][0], a1[mt][nt][0]));
            v0.y = __float2half_rn(fmaf(kLoInv, a2[mt][nt][1], a1[mt][nt][1]));
            v1.x = __float2half_rn(fmaf(kLoInv, a2[mt][nt][2], a1[mt][nt][2]));
            v1.y = __float2half_rn(fmaf(kLoInv, a2[mt][nt][3], a1[mt][nt][3]));
            *(__half2*)&g_M2[(size_t)j * Hn + k] = v0;
            *(__half2*)&g_M2[(size_t)(j + 8) * Hn + k] = v1;
        }
}

// ---------------------------------------------------------------------------
// v_kernel: V[i][j][b] = sum_k Mh[j][k]*Uo[i][b][k] + U[2i+2][j][b]
// CTA: 128j x (2 i's x 64b); grid (16, 128). Guard i < 255.
// ---------------------------------------------------------------------------
__global__ __launch_bounds__(512) void v_kernel() {
    extern __shared__ char sm[];
    const uint32_t sb = smem_u32(sm);
    const int j0 = blockIdx.x * 128;
    const int i0 = blockIdx.y * 2;
    const int tid = threadIdx.x;
    const int wid = tid >> 5, lane = tid & 31;
    const int mg = wid >> 2, nh = wid & 3;
    const int g8 = lane >> 2, tg = lane & 3;

    const uint32_t aOff = (uint32_t)(mg * 32 + (lane & 15)) * GRB + (lane >> 4) * 16;
    const uint32_t bOff =
        (uint32_t)(nh * 32 + (lane & 7) + ((lane >> 4) & 1) * 8) * GRB +
        ((lane >> 3) & 1) * 16;

    float acc[2][4][4] = {};
    for (int m0 = 0; m0 < Hn; m0 += 128) {
        #pragma unroll
        for (int p = 0; p < 4; p++) {
            int f = tid + p * 512;
            int r = f >> 4, c = f & 15;
            *(uint4*)(sm + r * GRB + c * 16) =
                *(const uint4*)&g_Mh[(size_t)(j0 + r) * Hn + m0 + c * 8];
            int il = r >> 6, b = r & 63;
            *(uint4*)(sm + GA + r * GRB + c * 16) =
                *(const uint4*)&g_Uo[(size_t)(i0 + il) * HB + (size_t)b * Hn + m0 + c * 8];
        }
        __syncthreads();
        #pragma unroll
        for (int kk = 0; kk < 8; kk++) {
            uint32_t A0[4], A1[4], Bv[4], Bw[4];
            ldsm4(A0, sb + aOff + kk * 32);
            ldsm4(A1, sb + aOff + kk * 32 + 16 * GRB);
            ldsm4(Bv, sb + GA + bOff + kk * 32);
            ldsm4(Bw, sb + GA + bOff + kk * 32 + 16 * GRB);
            mma16816(acc[0][0], A0, Bv[0], Bv[1]); mma16816(acc[0][1], A0, Bv[2], Bv[3]);
            mma16816(acc[0][2], A0, Bw[0], Bw[1]); mma16816(acc[0][3], A0, Bw[2], Bw[3]);
            mma16816(acc[1][0], A1, Bv[0], Bv[1]); mma16816(acc[1][1], A1, Bv[2], Bv[3]);
            mma16816(acc[1][2], A1, Bw[0], Bw[1]); mma16816(acc[1][3], A1, Bw[2], Bw[3]);
        }
        __syncthreads();
    }
    #pragma unroll
    for (int mt = 0; mt < 2; mt++)
        #pragma unroll
        for (int nt = 0; nt < 4; nt++) {
            int brow = nh * 32 + nt * 8 + tg * 2;
            int i = i0 + (brow >> 6), b = brow & 63;
            if (i >= 255) continue;
            int j = j0 + mg * 32 + mt * 16 + g8;
            size_t idx0 = (size_t)j * Bn + b, idx1 = (size_t)(j + 8) * Bn + b;
            float2 u0 = *(const float2*)&g_U[(size_t)(2 * i + 2) * HB + idx0];
            float2 u1 = *(const float2*)&g_U[(size_t)(2 * i + 2) * HB + idx1];
            *(float2*)&g_V[(size_t)i * HB + idx0] =
                make_float2(acc[mt][nt][0] + u0.x, acc[mt][nt][1] + u0.y);
            *(float2*)&g_V[(size_t)i * HB + idx1] =
                make_float2(acc[mt][nt][2] + u1.x, acc[mt][nt][3] + u1.y);
        }
}

// ---------------------------------------------------------------------------
// odd_kernel: h[2i+1][b][j] = fp16( sum_k Mh[j][k]*hist[2i][b][k] + U[2i+1][j][b] )
// CTA: 128j x (2 i's x 64b); grid (16, 128).
// ---------------------------------------------------------------------------
__global__ __launch_bounds__(512) void odd_kernel() {
    extern __shared__ char sm[];
    const uint32_t sb = smem_u32(sm);
    const int j0 = blockIdx.x * 128;
    const int i0 = blockIdx.y * 2;
    const int tid = threadIdx.x;
    const int wid = tid >> 5, lane = tid & 31;
    const int mg = wid >> 2, nh = wid & 3;
    const int g8 = lane >> 2, tg = lane & 3;

    const uint32_t aOff = (uint32_t)(mg * 32 + (lane & 15)) * GRB + (lane >> 4) * 16;
    const uint32_t bOff =
        (uint32_t)(nh * 32 + (lane & 7) + ((lane >> 4) & 1) * 8) * GRB +
        ((lane >> 3) & 1) * 16;

    float acc[2][4][4] = {};
    for (int m0 = 0; m0 < Hn; m0 += 128) {
        #pragma unroll
        for (int p = 0; p < 4; p++) {
            int f = tid + p * 512;
            int r = f >> 4, c = f & 15;
            *(uint4*)(sm + r * GRB + c * 16) =
                *(const uint4*)&g_Mh[(size_t)(j0 + r) * Hn + m0 + c * 8];
            int il = r >> 6, b = r & 63;
            *(uint4*)(sm + GA + r * GRB + c * 16) =
                *(const uint4*)&g_hist[(size_t)(2 * (i0 + il)) * HB +
                                       (size_t)b * Hn + m0 + c * 8];
        }
        __syncthreads();
        #pragma unroll
        for (int kk = 0; kk < 8; kk++) {
            uint32_t A0[4], A1[4], Bv[4], Bw[4];
            ldsm4(A0, sb + aOff + kk * 32);
            ldsm4(A1, sb + aOff + kk * 32 + 16 * GRB);
            ldsm4(Bv, sb + GA + bOff + kk * 32);
            ldsm4(Bw, sb + GA + bOff + kk * 32 + 16 * GRB);
            mma16816(acc[0][0], A0, Bv[0], Bv[1]); mma16816(acc[0][1], A0, Bv[2], Bv[3]);
            mma16816(acc[0][2], A0, Bw[0], Bw[1]); mma16816(acc[0][3], A0, Bw[2], Bw[3]);
            mma16816(acc[1][0], A1, Bv[0], Bv[1]); mma16816(acc[1][1], A1, Bv[2], Bv[3]);
            mma16816(acc[1][2], A1, Bw[0], Bw[1]); mma16816(acc[1][3], A1, Bw[2], Bw[3]);
        }
        __syncthreads();
    }
    // stage [j 128][brow 130pad] overlays A/B
    float (*stage2)[130] = (float (*)[130])sm;
    #pragma unroll
    for (int mt = 0; mt < 2; mt++)
        #pragma unroll
        for (int nt = 0; nt < 4; nt++) {
            int brow = nh * 32 + nt * 8 + tg * 2;
            int i = i0 + (brow >> 6), b = brow & 63;
            int jl = mg * 32 + mt * 16 + g8;
            float2 u0 = *(const float2*)&g_U[(size_t)(2 * i + 1) * HB +
                                             (size_t)(j0 + jl) * Bn + b];
            float2 u1 = *(const float2*)&g_U[(size_t)(2 * i + 1) * HB +
                                             (size_t)(j0 + jl + 8) * Bn + b];
            *(float2*)&stage2[jl][brow] =
                make_float2(acc[mt][nt][0] + u0.x, acc[mt][nt][1] + u0.y);
            *(float2*)&stage2[jl + 8][brow] =
                make_float2(acc[mt][nt][2] + u1.x, acc[mt][nt][3] + u1.y);
        }
    __syncthreads();
    #pragma unroll
    for (int il = 0; il < 2; il++) {
        int t = 2 * (i0 + il) + 1;
        int b = tid >> 3;
        #pragma unroll
        for (int p = 0; p < 8; p++) {
            int jj = (tid & 7) * 2 + p * 16;
            __half2 hv;
            hv.x = __float2half_rn(stage2[jj][il * 64 + b]);
            hv.y = __float2half_rn(stage2[jj + 1][il * 64 + b]);
            *(__half2*)&g_hist[(size_t)t * HB + (size_t)b * Hn + j0 + jj] = hv;
        }
    }
}

// ---------------------------------------------------------------------------
// persistent loop (R12 structure): 255 steps, t = 2,4,...,510.
// CTA (jt,kq): partial D[128j x 64b] = M2-slice x hist[t-2]-slice.
// Phase 2: h = sum(part) + V[(t>>1)-1]; write fp16 g_hist[t].
// ---------------------------------------------------------------------------
__global__ __launch_bounds__(NTHR, 1) void loop_kernel() {
    extern __shared__ char smem[];
    const uint32_t sb = smem_u32(smem);
    const int tid = threadIdx.x;
    const int wid = tid >> 5, lane = tid & 31;
    const int cta = blockIdx.x;
    const int jt = cta / KSPLIT, kq = cta % KSPLIT;
    const int j0 = jt * 128;
    const int ku = slice_units(kq);
    const int ku2 = ku * 2;
    const int kbase = slice_start16(kq) * 16;
    const int rc = cta * 16;

    const int mg = wid >> 1;
    const int nh = wid & 1;
    const int g8 = lane >> 2, tg = lane & 3;

    const int jl = (tid * 2) >> 6;
    const int bb = (tid * 2) & 63;
    const size_t ownIdx = (size_t)(rc + jl) * Bn + bb;

    // prologue: resident M2 slice -> SMEM
    for (int p = 0; p < 8; p++) {
        int f = tid + p * 512;
        int r = f >> 5, c = f & 31;
        if (c < ku2)
            *(uint4*)(smem + OFF_WH + r * ROWB + c * 16) =
                *(const uint4*)&g_M2[(size_t)(j0 + r) * Hn + kbase + c * 8];
    }
    __syncthreads();

    const uint32_t aLane =
        sb + OFF_WH + (uint32_t)(mg * 32 + (lane & 15)) * ROWB + (lane >> 4) * 16;
    const uint32_t bLane =
        sb + OFF_BH + (uint32_t)(nh * 32 + (lane & 7) + ((lane >> 4) & 1) * 8) * ROWB +
        ((lane >> 3) & 1) * 16;
    float (*stage)[66] = (float (*)[66])(smem + OFF_STG);

    for (int t = 2; t <= 510; t += 2) {
        const __half* hb = g_hist + (size_t)(t - 2) * HB;
        #pragma unroll
        for (int p = 0; p < 4; p++) {
            int f = tid + p * 512;
            int b = f >> 5, c = f & 31;
            if (c < ku2)
                *(uint4*)(smem + OFF_BH + b * ROWB + c * 16) =
                    __ldcg((const uint4*)&hb[(size_t)b * Hn + kbase + c * 8]);
        }
        __syncthreads();

        float acc[2][4][4] = {};
        if (wid < 8) {
            #pragma unroll 5
            for (int kk = 0; kk < ku; kk++) {
                uint32_t A0[4], A1[4], Bv[4], Bw[4];
                ldsm4(A0, aLane + kk * 32);
                ldsm4(A1, aLane + kk * 32 + 16 * ROWB);
                ldsm4(Bv, bLane + kk * 32);
                ldsm4(Bw, bLane + kk * 32 + 16 * ROWB);
                mma16816(acc[0][0], A0, Bv[0], Bv[1]);
                mma16816(acc[0][1], A0, Bv[2], Bv[3]);
                mma16816(acc[0][2], A0, Bw[0], Bw[1]);
                mma16816(acc[0][3], A0, Bw[2], Bw[3]);
                mma16816(acc[1][0], A1, Bv[0], Bv[1]);
                mma16816(acc[1][1], A1, Bv[2], Bv[3]);
                mma16816(acc[1][2], A1, Bw[0], Bw[1]);
                mma16816(acc[1][3], A1, Bw[2], Bw[3]);
            }
        }
        __syncthreads();

        if (wid < 8) {
            #pragma unroll
            for (int mt = 0; mt < 2; mt++)
                #pragma unroll
                for (int nt = 0; nt < 4; nt++) {
                    int r0 = mt * 16 + g8, cc = nt * 8 + tg * 2;
                    int j = j0 + mg * 32 + r0;
                    int bc = nh * 32 + cc;
                    __stcg((float2*)&g_part[((size_t)kq * Hn + j) * Bn + bc],
                           make_float2(acc[mt][nt][0], acc[mt][nt][1]));
                    __stcg((float2*)&g_part[((size_t)kq * Hn + j + 8) * Bn + bc],
                           make_float2(acc[mt][nt][2], acc[mt][nt][3]));
                }
        }

        float2 vv = make_float2(0.f, 0.f);
        if (cta < 128)
            vv = *(const float2*)&g_V[(size_t)((t >> 1) - 1) * HB + ownIdx];

        grid_sync_dev();

        if (cta < 128) {
            float2 s = vv;
            #pragma unroll
            for (int q = 0; q < KSPLIT; q++) {
                float2 v = __ldcg((const float2*)&g_part[(size_t)q * HB + ownIdx]);
                s.x += v.x; s.y += v.y;
            }
            *(float2*)&stage[jl][bb] = s;
            __syncthreads();
            int b = tid >> 3, kk = tid & 7;
            __half2 hv;
            hv.x = __float2half_rn(stage[kk * 2][b]);
            hv.y = __float2half_rn(stage[kk * 2 + 1][b]);
            *(__half2*)&g_hist[(size_t)t * HB + (size_t)b * Hn + rc + kk * 2] = hv;
        }

        grid_sync_dev();
    }
}

// ---------------------------------------------------------------------------
// out[b][t][o] = sum_k g_hist[t][b][k] * woT[o][k]
// ---------------------------------------------------------------------------
__global__ __launch_bounds__(256) void out_kernel(float* __restrict__ out) {
    extern __shared__ char sm[];
    const uint32_t sb = smem_u32(sm);
    const int t = blockIdx.x, tid = threadIdx.x;
    const int wid = tid >> 5, lane = tid & 31;
    const int mg = wid >> 2, nh = wid & 3;

    const uint32_t aLane = (uint32_t)(mg * 32 + (lane & 15)) * GRB + (lane >> 4) * 16;
    const uint32_t bLane =
        (uint32_t)(nh * 32 + (lane & 7) + ((lane >> 4) & 1) * 8) * GRB +
        ((lane >> 3) & 1) * 16;
    const int g8 = lane >> 2, tg = lane & 3;

    float acc[2][4][4] = {};
    const __half* hsrc = g_hist + (size_t)t * HB;

    for (int k0 = 0; k0 < Hn; k0 += 128) {
        #pragma unroll
        for (int p = 0; p < 4; p++) {
            int f = tid + p * 256;
            int r = f >> 4, c = f & 15;
            *(uint4*)(sm + r * GRB + c * 16) =
                *(const uint4*)&hsrc[(size_t)r * Hn + k0 + c * 8];
        }
        #pragma unroll
        for (int p = 0; p < 8; p++) {
            int f = tid + p * 256;
            int r = f >> 4, c = f & 15;
            *(uint4*)(sm + OFF_OB + r * GRB + c * 16) =
                *(const uint4*)&g_woT[(size_t)r * Hn + k0 + c * 8];
        }
        __syncthreads();
        const uint32_t aB = sb + aLane, bB = sb + OFF_OB + bLane;
        #pragma unroll
        for (int kk = 0; kk < 8; kk++) {
            uint32_t A0[4], A1[4], Bv[4], Bw[4];
            ldsm4(A0, aB + kk * 32);
            ldsm4(A1, aB + kk * 32 + 16 * GRB);
            ldsm4(Bv, bB + kk * 32);
            ldsm4(Bw, bB + kk * 32 + 16 * GRB);
            mma16816(acc[0][0], A0, Bv[0], Bv[1]);
            mma16816(acc[0][1], A0, Bv[2], Bv[3]);
            mma16816(acc[0][2], A0, Bw[0], Bw[1]);
            mma16816(acc[0][3], A0, Bw[2], Bw[3]);
            mma16816(acc[1][0], A1, Bv[0], Bv[1]);
            mma16816(acc[1][1], A1, Bv[2], Bv[3]);
            mma16816(acc[1][2], A1, Bw[0], Bw[1]);
            mma16816(acc[1][3], A1, Bw[2], Bw[3]);
        }
        __syncthreads();
    }

    #pragma unroll
    for (int mt = 0; mt < 2; mt++)
        #pragma unroll
        for (int nt = 0; nt < 4; nt++) {
            int r0 = mt * 16 + g8, cc = nt * 8 + tg * 2;
            int b = mg * 32 + r0;
            int o = nh * 32 + cc;
            *(float2*)&out[((size_t)b * Sn + t) * On + o] =
                make_float2(acc[mt][nt][0], acc[mt][nt][1]);
            *(float2*)&out[((size_t)(b + 8) * Sn + t) * On + o] =
                make_float2(acc[mt][nt][2], acc[mt][nt][3]);
        }
}

// ---------------------------------------------------------------------------
extern "C" void kernel_launch(void* const* d_in, const int* in_sizes, int n_in,
                              void* d_out, int out_size) {
    const float* x     = (const float*)d_in[0];
    const float* noise = (const float*)d_in[1];
    const float* wi    = (const float*)d_in[2];
    const float* wrec  = (const float*)d_in[3];
    const float* wout  = (const float*)d_in[4];
    const float* g     = (const float*)d_in[5];
    const float* h0    = (const float*)d_in[6];
    float* out = (float*)d_out;

    cudaFuncSetAttribute(loop_kernel, cudaFuncAttributeMaxDynamicSharedMemorySize,
                         SMEM_TOTAL);
    cudaFuncSetAttribute(u_kernel, cudaFuncAttributeMaxDynamicSharedMemorySize, USMEM);
    cudaFuncSetAttribute(out_kernel, cudaFuncAttributeMaxDynamicSharedMemorySize, OSMEM);
    cudaFuncSetAttribute(mm2_kernel, cudaFuncAttributeMaxDynamicSharedMemorySize,
                         MM2_SMEM);
    cudaFuncSetAttribute(v_kernel, cudaFuncAttributeMaxDynamicSharedMemorySize, VO_SMEM);
    cudaFuncSetAttribute(odd_kernel, cudaFuncAttributeMaxDynamicSharedMemorySize,
                         VO_SMEM);

    mprep_kernel<<<dim3(Hn / 32, Hn / 32), dim3(32, 32)>>>(wrec, g);
    wtprep_kernel<<<dim3(Hn / 32, On / 32), dim3(32, 32)>>>(wout);
    witprep_kernel<<<dim3(In / 32, Hn / 32), dim3(32, 32)>>>(wi);
    xhprep_kernel<<<Bn * Sn * In / 256, 256>>>(x);
    hbinit_kernel<<<HB / 256, 256>>>(h0);
    u_kernel<<<dim3(Hn / 128, Sn - 1), 256, USMEM>>>(noise);
    mm2_kernel<<<dim3(16, 16), 512, MM2_SMEM>>>();
    v_kernel<<<dim3(16, 128), 512, VO_SMEM>>>();
    loop_kernel<<<NCTA, NTHR, SMEM_TOTAL>>>();
    odd_kernel<<<dim3(16, 128), 512, VO_SMEM>>>();
    out_kernel<<<Sn, 256, OSMEM>>>(out);
}

// round 16
// speedup vs baseline: 1.4783x; 1.0163x over previous
#include <cuda_runtime.h>
#include <cuda_fp16.h>
#include <cstdint>
#include <cstddef>

// ---------------------------------------------------------------------------
// RNN_fish, R16: step-doubled persistent HMMA kernel (R15) with operand-reuse
// rework of the parallel GEMMs:
//   v/odd: 4 i's per CTA (A reused across 256 rows), u: 4 t's per CTA
//   (wiT resident). Loop arithmetic identical to R15.
// ---------------------------------------------------------------------------

namespace {
constexpr int Bn = 64;
constexpr int Sn = 512;
constexpr int In = 128;
constexpr int Hn = 2048;
constexpr int On = 128;
constexpr int KSPLIT = 9;
constexpr int NCTA = 144;
constexpr int NTHR = 512;
constexpr int HB = Hn * Bn;
constexpr float kNoise = 0.005f;
constexpr float kAlpha = 0.2f;
constexpr float kLoInv = 1.0f / 4096.0f;

__host__ __device__ __forceinline__ int slice_units(int kq) { return 14 + (kq < 2); }
__host__ __device__ __forceinline__ int slice_start16(int kq) {
    return kq * 14 + (kq < 2 ? kq : 2);
}

// loop smem
constexpr int ROWB = 528;
constexpr int OFF_WH = 0;
constexpr int OFF_BH = OFF_WH + 128 * ROWB;
constexpr int OFF_STG = OFF_BH;
constexpr int SMEM_TOTAL = OFF_BH + 64 * ROWB;  // 101376

// generic 128-wide GEMM smem
constexpr int GRB = 272;
constexpr int GA = 128 * GRB;                   // 34816
// mm2: Ah,Al,Bh,Bl
constexpr int MM2_SMEM = 4 * GA;                // 139264
// v/odd: A (128 rows) + B (256 rows); odd stage overlays
constexpr int V2_SMEM = GA + 256 * GRB;         // 104448
// u-kernel: x(64) + wiTh(128) + wiTl(128) + stage
constexpr int UOFF_BH = 64 * GRB;               // 17408
constexpr int UOFF_BL = UOFF_BH + 128 * GRB;    // 52224
constexpr int UOFF_ST = UOFF_BL + 128 * GRB;    // 87040
constexpr int USMEM = UOFF_ST + 64 * 132 * 4;   // 120832
// out-kernel
constexpr int OFF_OB = 64 * GRB;
constexpr int OSMEM = OFF_OB + 128 * GRB;       // 52224
}

// device globals
__device__ float g_U[(size_t)Sn * Hn * Bn];          // [t][j][b] fp32 (t>=1)
__device__ float g_V[(size_t)255 * Hn * Bn];         // [i][j][b] fp32
__device__ float g_part[(size_t)KSPLIT * Hn * Bn];   // [q][j][b]
__device__ __half g_Mh[(size_t)Hn * Hn];             // [j][k] fp16 hi of M
__device__ __half g_Ml[(size_t)Hn * Hn];             // [j][k] 4096*lo
__device__ __half g_MTh[(size_t)Hn * Hn];            // [k][j]
__device__ __half g_MTl[(size_t)Hn * Hn];            // [k][j]
__device__ __half g_M2[(size_t)Hn * Hn];             // [j][k] fp16 M^2
__device__ __half g_hist[(size_t)Sn * Bn * Hn];      // [t][b][k] fp16 h
__device__ __half g_Uo[(size_t)256 * Bn * Hn];       // [(t-1)/2][b][k] fp16, odd t
__device__ __half g_woT[(size_t)On * Hn];            // [o][k]
__device__ __half g_wiTh[(size_t)Hn * In];
__device__ __half g_wiTl[(size_t)Hn * In];
__device__ __half g_xh[(size_t)Bn * Sn * In];        // [b][t][i]
__device__ unsigned g_bar_count;
__device__ unsigned g_bar_gen;

// ---- helpers ----
__device__ __forceinline__ uint32_t smem_u32(const void* p) {
    uint32_t a;
    asm("{ .reg .u64 t; cvta.to.shared.u64 t, %1; cvt.u32.u64 %0, t; }" : "=r"(a) : "l"(p));
    return a;
}
__device__ __forceinline__ void ldsm4(uint32_t a[4], uint32_t addr) {
    asm volatile("ldmatrix.sync.aligned.m8n8.x4.shared.b16 {%0,%1,%2,%3}, [%4];"
                 : "=r"(a[0]), "=r"(a[1]), "=r"(a[2]), "=r"(a[3]) : "r"(addr));
}
__device__ __forceinline__ void mma16816(float c[4], const uint32_t a[4],
                                         uint32_t b0, uint32_t b1) {
    asm volatile("mma.sync.aligned.m16n8k16.row.col.f32.f16.f16.f32 "
                 "{%0,%1,%2,%3}, {%4,%5,%6,%7}, {%8,%9}, {%0,%1,%2,%3};"
                 : "+f"(c[0]), "+f"(c[1]), "+f"(c[2]), "+f"(c[3])
                 : "r"(a[0]), "r"(a[1]), "r"(a[2]), "r"(a[3]), "r"(b0), "r"(b1));
}

// flat grid barrier (proven)
__device__ __forceinline__ void grid_sync_dev() {
    __syncthreads();
    if (threadIdx.x == 0) {
        __threadfence();
        unsigned old, my;
        asm volatile("ld.acquire.gpu.global.u32 %0, [%1];"
                     : "=r"(old) : "l"(&g_bar_gen) : "memory");
        asm volatile("atom.release.gpu.global.add.u32 %0, [%1], %2;"
                     : "=r"(my) : "l"(&g_bar_count), "r"(1u) : "memory");
        if (my == (unsigned)(NCTA - 1)) {
            asm volatile("st.global.u32 [%0], %1;" :: "l"(&g_bar_count), "r"(0u) : "memory");
            asm volatile("red.release.gpu.global.add.u32 [%0], %1;"
                         :: "l"(&g_bar_gen), "r"(1u) : "memory");
        } else {
            unsigned cur;
            do {
                asm volatile("ld.acquire.gpu.global.u32 %0, [%1];"
                             : "=r"(cur) : "l"(&g_bar_gen) : "memory");
            } while (cur == old);
        }
        __threadfence();
    }
    __syncthreads();
}

// ---------------------------------------------------------------------------
// prep kernels
// ---------------------------------------------------------------------------
__global__ __launch_bounds__(1024) void mprep_kernel(const float* __restrict__ wrec,
                                                     const float* __restrict__ g) {
    __shared__ float sh[32][33], sl[32][33];
    int tx = threadIdx.x, ty = threadIdx.y;
    int j0 = blockIdx.y * 32, k0 = blockIdx.x * 32;
    int j = j0 + ty, k = k0 + tx;
    float v = kAlpha * g[k] * wrec[(size_t)j * Hn + k];
    if (j == k) v += 1.0f - kAlpha;
    __half hi = __float2half_rn(v);
    float lo = (v - __half2float(hi)) * 4096.0f;
    g_Mh[(size_t)j * Hn + k] = hi;
    g_Ml[(size_t)j * Hn + k] = __float2half_rn(lo);
    sh[ty][tx] = __half2float(hi);
    sl[ty][tx] = lo;
    __syncthreads();
    g_MTh[(size_t)(k0 + ty) * Hn + j0 + tx] = __float2half_rn(sh[tx][ty]);
    g_MTl[(size_t)(k0 + ty) * Hn + j0 + tx] = __float2half_rn(sl[tx][ty]);
}

__global__ void hbinit_kernel(const float* __restrict__ h0) {
    int n = blockIdx.x * blockDim.x + threadIdx.x;
    g_hist[n] = __float2half_rn(h0[n & (Hn - 1)]);
}

__global__ void xhprep_kernel(const float* __restrict__ x) {
    int n = blockIdx.x * blockDim.x + threadIdx.x;
    g_xh[n] = __float2half_rn(x[n]);
}

__global__ __launch_bounds__(1024) void wtprep_kernel(const float* __restrict__ wout) {
    __shared__ float s[32][33];
    int tx = threadIdx.x, ty = threadIdx.y;
    int k0 = blockIdx.x * 32, o0 = blockIdx.y * 32;
    s[ty][tx] = wout[(size_t)(k0 + ty) * On + o0 + tx];
    __syncthreads();
    g_woT[(size_t)(o0 + ty) * Hn + k0 + tx] = __float2half_rn(s[tx][ty]);
}

__global__ __launch_bounds__(1024) void witprep_kernel(const float* __restrict__ wi) {
    __shared__ float s[32][33];
    int tx = threadIdx.x, ty = threadIdx.y;
    int i0 = blockIdx.x * 32, j0 = blockIdx.y * 32;
    s[ty][tx] = wi[(size_t)(i0 + ty) * Hn + j0 + tx];
    __syncthreads();
    float v = s[tx][ty];
    __half hi = __float2half_rn(v);
    g_wiTh[(size_t)(j0 + ty) * In + i0 + tx] = hi;
    g_wiTl[(size_t)(j0 + ty) * In + i0 + tx] =
        __float2half_rn((v - __half2float(hi)) * 4096.0f);
}

// ---------------------------------------------------------------------------
// u_kernel: 4 t's per CTA, wiT resident. U[t][j][b] fp32; odd t -> g_Uo fp16.
// ---------------------------------------------------------------------------
__global__ __launch_bounds__(256) void u_kernel(const float* __restrict__ noise) {
    extern __shared__ char sm[];
    const uint32_t sb = smem_u32(sm);
    const int jt = blockIdx.x;
    const int j0 = jt * 128;
    const int tid = threadIdx.x;
    const int wid = tid >> 5, lane = tid & 31;
    const int mgb = wid >> 2, njw = wid & 3;
    const int g8 = lane >> 2, tg = lane & 3;

    // resident weights
    #pragma unroll
    for (int p = 0; p < 8; p++) {
        int f = tid + p * 256;
        int r = f >> 4, c = f & 15;
        size_t gi = (size_t)(j0 + r) * In + c * 8;
        *(uint4*)(sm + UOFF_BH + r * GRB + c * 16) = *(const uint4*)&g_wiTh[gi];
        *(uint4*)(sm + UOFF_BL + r * GRB + c * 16) = *(const uint4*)&g_wiTl[gi];
    }

    const uint32_t aLane =
        sb + (uint32_t)(mgb * 32 + (lane & 15)) * GRB + (lane >> 4) * 16;
    const uint32_t bLane =
        (uint32_t)(njw * 32 + (lane & 7) + ((lane >> 4) & 1) * 8) * GRB +
        ((lane >> 3) & 1) * 16;
    float (*stage)[132] = (float (*)[132])(sm + UOFF_ST);

    for (int r4 = 0; r4 < 4; r4++) {
        int t = blockIdx.y * 4 + 1 + r4;
        if (t >= Sn) break;

        #pragma unroll
        for (int p = 0; p < 4; p++) {
            int f = tid + p * 256;
            int r = f >> 4, c = f & 15;
            *(uint4*)(sm + r * GRB + c * 16) =
                *(const uint4*)&g_xh[((size_t)r * Sn + (t - 1)) * In + c * 8];
        }
        __syncthreads();

        float a1[2][4][4] = {}, a2[2][4][4] = {};
        #pragma unroll
        for (int kk = 0; kk < 8; kk++) {
            uint32_t A0[4], A1[4], Bv[4], Bw[4];
            ldsm4(A0, aLane + kk * 32);
            ldsm4(A1, aLane + kk * 32 + 16 * GRB);
            ldsm4(Bv, sb + UOFF_BH + bLane + kk * 32);
            ldsm4(Bw, sb + UOFF_BH + bLane + kk * 32 + 16 * GRB);
            mma16816(a1[0][0], A0, Bv[0], Bv[1]); mma16816(a1[0][1], A0, Bv[2], Bv[3]);
            mma16816(a1[0][2], A0, Bw[0], Bw[1]); mma16816(a1[0][3], A0, Bw[2], Bw[3]);
            mma16816(a1[1][0], A1, Bv[0], Bv[1]); mma16816(a1[1][1], A1, Bv[2], Bv[3]);
            mma16816(a1[1][2], A1, Bw[0], Bw[1]); mma16816(a1[1][3], A1, Bw[2], Bw[3]);
            ldsm4(Bv, sb + UOFF_BL + bLane + kk * 32);
            ldsm4(Bw, sb + UOFF_BL + bLane + kk * 32 + 16 * GRB);
            mma16816(a2[0][0], A0, Bv[0], Bv[1]); mma16816(a2[0][1], A0, Bv[2], Bv[3]);
            mma16816(a2[0][2], A0, Bw[0], Bw[1]); mma16816(a2[0][3], A0, Bw[2], Bw[3]);
            mma16816(a2[1][0], A1, Bv[0], Bv[1]); mma16816(a2[1][1], A1, Bv[2], Bv[3]);
            mma16816(a2[1][2], A1, Bw[0], Bw[1]); mma16816(a2[1][3], A1, Bw[2], Bw[3]);
        }
        __syncthreads();

        #pragma unroll
        for (int mt = 0; mt < 2; mt++)
            #pragma unroll
            for (int nt = 0; nt < 4; nt++) {
                int rb = mgb * 32 + mt * 16 + g8;
                int jc = njw * 32 + nt * 8 + tg * 2;
                stage[rb][jc]     = fmaf(kLoInv, a2[mt][nt][0], a1[mt][nt][0]);
                stage[rb][jc + 1] = fmaf(kLoInv, a2[mt][nt][1], a1[mt][nt][1]);
                stage[rb + 8][jc]     = fmaf(kLoInv, a2[mt][nt][2], a1[mt][nt][2]);
                stage[rb + 8][jc + 1] = fmaf(kLoInv, a2[mt][nt][3], a1[mt][nt][3]);
            }
        __syncthreads();

        #pragma unroll
        for (int rep = 0; rep < 8; rep++) {
            int b = wid * 8 + rep;
            #pragma unroll
            for (int c = 0; c < 4; c++) {
                int j = c * 32 + lane;
                float nv = noise[((size_t)b * Sn + (t - 1)) * Hn + j0 + j];
                stage[b][j] = fmaf(kAlpha, stage[b][j], kNoise * nv);
            }
        }
        __syncthreads();

        {   // fp32 [j][b]
            int j = tid >> 1, bh = (tid & 1) * 32;
            #pragma unroll
            for (int bc = 0; bc < 8; bc++) {
                int b0 = bh + bc * 4;
                float4 v = make_float4(stage[b0][j], stage[b0 + 1][j],
                                       stage[b0 + 2][j], stage[b0 + 3][j]);
                *(float4*)&g_U[((size_t)t * Hn + j0 + j) * Bn + b0] = v;
            }
        }
        if (t & 1) {
            int ui = (t - 1) >> 1;
            int b = tid >> 2;
            #pragma unroll
            for (int p = 0; p < 16; p++) {
                int jj = (tid & 3) * 2 + p * 8;
                __half2 hv;
                hv.x = __float2half_rn(stage[b][jj]);
                hv.y = __float2half_rn(stage[b][jj + 1]);
                *(__half2*)&g_Uo[(size_t)ui * HB + (size_t)b * Hn + j0 + jj] = hv;
            }
        }
        __syncthreads();   // stage reads done before next iteration rewrites
    }
}

// ---------------------------------------------------------------------------
// mm2_kernel: M2 = M*M, 3 chains. Unchanged from R15.
// ---------------------------------------------------------------------------
__global__ __launch_bounds__(512) void mm2_kernel() {
    extern __shared__ char sm[];
    const uint32_t sb = smem_u32(sm);
    const int j0 = blockIdx.x * 128, k0 = blockIdx.y * 128;
    const int tid = threadIdx.x;
    const int wid = tid >> 5, lane = tid & 31;
    const int mg = wid >> 2, nh = wid & 3;
    const int g8 = lane >> 2, tg = lane & 3;

    const uint32_t aOff = (uint32_t)(mg * 32 + (lane & 15)) * GRB + (lane >> 4) * 16;
    const uint32_t bOff =
        (uint32_t)(nh * 32 + (lane & 7) + ((lane >> 4) & 1) * 8) * GRB +
        ((lane >> 3) & 1) * 16;

    float a1[2][4][4] = {}, a2[2][4][4] = {};
    for (int m0 = 0; m0 < Hn; m0 += 128) {
        #pragma unroll
        for (int p = 0; p < 4; p++) {
            int f = tid + p * 512;
            int r = f >> 4, c = f & 15;
            size_t ga = (size_t)(j0 + r) * Hn + m0 + c * 8;
            size_t gb = (size_t)(k0 + r) * Hn + m0 + c * 8;
            *(uint4*)(sm + 0 * GA + r * GRB + c * 16) = *(const uint4*)&g_Mh[ga];
            *(uint4*)(sm + 1 * GA + r * GRB + c * 16) = *(const uint4*)&g_Ml[ga];
            *(uint4*)(sm + 2 * GA + r * GRB + c * 16) = *(const uint4*)&g_MTh[gb];
            *(uint4*)(sm + 3 * GA + r * GRB + c * 16) = *(const uint4*)&g_MTl[gb];
        }
        __syncthreads();
        #pragma unroll
        for (int kk = 0; kk < 8; kk++) {
            uint32_t Ah0[4], Ah1[4], Al0[4], Al1[4], Bh0[4], Bh1[4], Bl0[4], Bl1[4];
            ldsm4(Ah0, sb + 0 * GA + aOff + kk * 32);
            ldsm4(Ah1, sb + 0 * GA + aOff + kk * 32 + 16 * GRB);
            ldsm4(Al0, sb + 1 * GA + aOff + kk * 32);
            ldsm4(Al1, sb + 1 * GA + aOff + kk * 32 + 16 * GRB);
            ldsm4(Bh0, sb + 2 * GA + bOff + kk * 32);
            ldsm4(Bh1, sb + 2 * GA + bOff + kk * 32 + 16 * GRB);
            ldsm4(Bl0, sb + 3 * GA + bOff + kk * 32);
            ldsm4(Bl1, sb + 3 * GA + bOff + kk * 32 + 16 * GRB);
            mma16816(a1[0][0], Ah0, Bh0[0], Bh0[1]); mma16816(a1[0][1], Ah0, Bh0[2], Bh0[3]);
            mma16816(a1[0][2], Ah0, Bh1[0], Bh1[1]); mma16816(a1[0][3], Ah0, Bh1[2], Bh1[3]);
            mma16816(a1[1][0], Ah1, Bh0[0], Bh0[1]); mma16816(a1[1][1], Ah1, Bh0[2], Bh0[3]);
            mma16816(a1[1][2], Ah1, Bh1[0], Bh1[1]); mma16816(a1[1][3], Ah1, Bh1[2], Bh1[3]);
            mma16816(a2[0][0], Ah0, Bl0[0], Bl0[1]); mma16816(a2[0][1], Ah0, Bl0[2], Bl0[3]);
            mma16816(a2[0][2], Ah0, Bl1[0], Bl1[1]); mma16816(a2[0][3], Ah0, Bl1[2], Bl1[3]);
            mma16816(a2[1][0], Ah1, Bl0[0], Bl0[1]); mma16816(a2[1][1], Ah1, Bl0[2], Bl0[3]);
            mma16816(a2[1][2], Ah1, Bl1[0], Bl1[1]); mma16816(a2[1][3], Ah1, Bl1[2], Bl1[3]);
            mma16816(a2[0][0], Al0, Bh0[0], Bh0[1]); mma16816(a2[0][1], Al0, Bh0[2], Bh0[3]);
            mma16816(a2[0][2], Al0, Bh1[0], Bh1[1]); mma16816(a2[0][3], Al0, Bh1[2], Bh1[3]);
            mma16816(a2[1][0], Al1, Bh0[0], Bh0[1]); mma16816(a2[1][1], Al1, Bh0[2], Bh0[3]);
            mma16816(a2[1][2], Al1, Bh1[0], Bh1[1]); mma16816(a2[1][3], Al1, Bh1[2], Bh1[3]);
        }
        __syncthreads();
    }
    #pragma unroll
    for (int mt = 0; mt < 2; mt++)
        #pragma unroll
        for (int nt = 0; nt < 4; nt++) {
            int j = j0 + mg * 32 + mt * 16 + g8;
            int k = k0 + nh * 32 + nt * 8 + tg * 2;
            __half2 v0, v1;
            v0.x = __float2half_rn(fmaf(kLoInv, a2[mt][nt][0], a1[mt][nt][0]));
            v0.y = __float2half_rn(fmaf(kLoInv, a2[mt][nt][1], a1[mt][nt][1]));
            v1.x = __float2half_rn(fmaf(kLoInv, a2[mt][nt][2], a1[mt][nt][2]));
            v1.y = __float2half_rn(fmaf(kLoInv, a2[mt][nt][3], a1[mt][nt][3]));
            *(__half2*)&g_M2[(size_t)j * Hn + k] = v0;
            *(__half2*)&g_M2[(size_t)(j + 8) * Hn + k] = v1;
        }
}

// ---------------------------------------------------------------------------
// v_kernel: V[i][j][b] = sum_k Mh[j][k]*Uo[i][b][k] + U[2i+2][j][b]
// 4 i's per CTA (256 B rows); grid (16, 64); A reused across both row-halves.
// ---------------------------------------------------------------------------
__global__ __launch_bounds__(512) void v_kernel() {
    extern __shared__ char sm[];
    const uint32_t sb = smem_u32(sm);
    const int j0 = blockIdx.x * 128;
    const int i0 = blockIdx.y * 4;
    const int tid = threadIdx.x;
    const int wid = tid >> 5, lane = tid & 31;
    const int mg = wid >> 2, nh = wid & 3;
    const int g8 = lane >> 2, tg = lane & 3;

    const uint32_t aOff = (uint32_t)(mg * 32 + (lane & 15)) * GRB + (lane >> 4) * 16;
    const uint32_t bOff =
        (uint32_t)(nh * 32 + (lane & 7) + ((lane >> 4) & 1) * 8) * GRB +
        ((lane >> 3) & 1) * 16;

    float acc[2][2][4][4] = {};
    for (int m0 = 0; m0 < Hn; m0 += 128) {
        #pragma unroll
        for (int p = 0; p < 4; p++) {
            int f = tid + p * 512;              // A: 2048 chunks
            int r = f >> 4, c = f & 15;
            *(uint4*)(sm + r * GRB + c * 16) =
                *(const uint4*)&g_Mh[(size_t)(j0 + r) * Hn + m0 + c * 8];
        }
        #pragma unroll
        for (int p = 0; p < 8; p++) {
            int f = tid + p * 512;              // B: 4096 chunks (256 rows)
            int r = f >> 4, c = f & 15;
            int il = r >> 6, b = r & 63;
            *(uint4*)(sm + GA + r * GRB + c * 16) =
                *(const uint4*)&g_Uo[(size_t)(i0 + il) * HB + (size_t)b * Hn + m0 + c * 8];
        }
        __syncthreads();
        #pragma unroll
        for (int kk = 0; kk < 8; kk++) {
            uint32_t A0[4], A1[4];
            ldsm4(A0, sb + aOff + kk * 32);
            ldsm4(A1, sb + aOff + kk * 32 + 16 * GRB);
            #pragma unroll
            for (int hf = 0; hf < 2; hf++) {
                uint32_t Bv[4], Bw[4];
                uint32_t bb = sb + GA + hf * 128 * GRB + bOff + kk * 32;
                ldsm4(Bv, bb);
                ldsm4(Bw, bb + 16 * GRB);
                mma16816(acc[hf][0][0], A0, Bv[0], Bv[1]);
                mma16816(acc[hf][0][1], A0, Bv[2], Bv[3]);
                mma16816(acc[hf][0][2], A0, Bw[0], Bw[1]);
                mma16816(acc[hf][0][3], A0, Bw[2], Bw[3]);
                mma16816(acc[hf][1][0], A1, Bv[0], Bv[1]);
                mma16816(acc[hf][1][1], A1, Bv[2], Bv[3]);
                mma16816(acc[hf][1][2], A1, Bw[0], Bw[1]);
                mma16816(acc[hf][1][3], A1, Bw[2], Bw[3]);
            }
        }
        __syncthreads();
    }
    #pragma unroll
    for (int hf = 0; hf < 2; hf++)
        #pragma unroll
        for (int mt = 0; mt < 2; mt++)
            #pragma unroll
            for (int nt = 0; nt < 4; nt++) {
                int brow = hf * 128 + nh * 32 + nt * 8 + tg * 2;
                int i = i0 + (brow >> 6), b = brow & 63;
                if (i > 254) continue;
                int j = j0 + mg * 32 + mt * 16 + g8;
                size_t idx0 = (size_t)j * Bn + b, idx1 = (size_t)(j + 8) * Bn + b;
                float2 u0 = *(const float2*)&g_U[(size_t)(2 * i + 2) * HB + idx0];
                float2 u1 = *(const float2*)&g_U[(size_t)(2 * i + 2) * HB + idx1];
                *(float2*)&g_V[(size_t)i * HB + idx0] =
                    make_float2(acc[hf][mt][nt][0] + u0.x, acc[hf][mt][nt][1] + u0.y);
                *(float2*)&g_V[(size_t)i * HB + idx1] =
                    make_float2(acc[hf][mt][nt][2] + u1.x, acc[hf][mt][nt][3] + u1.y);
            }
}

// ---------------------------------------------------------------------------
// odd_kernel: h[2i+1][b][j] = fp16( sum_k Mh[j][k]*hist[2i][b][k] + U[2i+1][j][b] )
// 4 i's per CTA; grid (16, 64); epilogue staged per 128-row half.
// ---------------------------------------------------------------------------
__global__ __launch_bounds__(512) void odd_kernel() {
    extern __shared__ char sm[];
    const uint32_t sb = smem_u32(sm);
    const int j0 = blockIdx.x * 128;
    const int i0 = blockIdx.y * 4;
    const int tid = threadIdx.x;
    const int wid = tid >> 5, lane = tid & 31;
    const int mg = wid >> 2, nh = wid & 3;
    const int g8 = lane >> 2, tg = lane & 3;

    const uint32_t aOff = (uint32_t)(mg * 32 + (lane & 15)) * GRB + (lane >> 4) * 16;
    const uint32_t bOff =
        (uint32_t)(nh * 32 + (lane & 7) + ((lane >> 4) & 1) * 8) * GRB +
        ((lane >> 3) & 1) * 16;

    float acc[2][2][4][4] = {};
    for (int m0 = 0; m0 < Hn; m0 += 128) {
        #pragma unroll
        for (int p = 0; p < 4; p++) {
            int f = tid + p * 512;
            int r = f >> 4, c = f & 15;
            *(uint4*)(sm + r * GRB + c * 16) =
                *(const uint4*)&g_Mh[(size_t)(j0 + r) * Hn + m0 + c * 8];
        }
        #pragma unroll
        for (int p = 0; p < 8; p++) {
            int f = tid + p * 512;
            int r = f >> 4, c = f & 15;
            int il = r >> 6, b = r & 63;
            *(uint4*)(sm + GA + r * GRB + c * 16) =
                *(const uint4*)&g_hist[(size_t)(2 * (i0 + il)) * HB +
                                       (size_t)b * Hn + m0 + c * 8];
        }
        __syncthreads();
        #pragma unroll
        for (int kk = 0; kk < 8; kk++) {
            uint32_t A0[4], A1[4];
            ldsm4(A0, sb + aOff + kk * 32);
            ldsm4(A1, sb + aOff + kk * 32 + 16 * GRB);
            #pragma unroll
            for (int hf = 0; hf < 2; hf++) {
                uint32_t Bv[4], Bw[4];
                uint32_t bb = sb + GA + hf * 128 * GRB + bOff + kk * 32;
                ldsm4(Bv, bb);
                ldsm4(Bw, bb + 16 * GRB);
                mma16816(acc[hf][0][0], A0, Bv[0], Bv[1]);
                mma16816(acc[hf][0][1], A0, Bv[2], Bv[3]);
                mma16816(acc[hf][0][2], A0, Bw[0], Bw[1]);
                mma16816(acc[hf][0][3], A0, Bw[2], Bw[3]);
                mma16816(acc[hf][1][0], A1, Bv[0], Bv[1]);
                mma16816(acc[hf][1][1], A1, Bv[2], Bv[3]);
                mma16816(acc[hf][1][2], A1, Bw[0], Bw[1]);
                mma16816(acc[hf][1][3], A1, Bw[2], Bw[3]);
            }
        }
        __syncthreads();
    }

    float (*stage2)[130] = (float (*)[130])sm;   // overlays A+B
    #pragma unroll
    for (int hf = 0; hf < 2; hf++) {
        #pragma unroll
        for (int mt = 0; mt < 2; mt++)
            #pragma unroll
            for (int nt = 0; nt < 4; nt++) {
                int br = nh * 32 + nt * 8 + tg * 2;          // 0..127
                int grow = hf * 128 + br;
                int i = i0 + (grow >> 6), b = grow & 63;
                int jl = mg * 32 + mt * 16 + g8;
                float2 u0 = *(const float2*)&g_U[(size_t)(2 * i + 1) * HB +
                                                 (size_t)(j0 + jl) * Bn + b];
                float2 u1 = *(const float2*)&g_U[(size_t)(2 * i + 1) * HB +
                                                 (size_t)(j0 + jl + 8) * Bn + b];
                *(float2*)&stage2[jl][br] =
                    make_float2(acc[hf][mt][nt][0] + u0.x, acc[hf][mt][nt][1] + u0.y);
                *(float2*)&stage2[jl + 8][br] =
                    make_float2(acc[hf][mt][nt][2] + u1.x, acc[hf][mt][nt][3] + u1.y);
            }
        __syncthreads();
        #pragma unroll
        for (int il = 0; il < 2; il++) {
            int t = 2 * (i0 + hf * 2 + il) + 1;
            int b = tid >> 3;
            #pragma unroll
            for (int p = 0; p < 8; p++) {
                int jj = (tid & 7) * 2 + p * 16;
                __half2 hv;
                hv.x = __float2half_rn(stage2[jj][il * 64 + b]);
                hv.y = __float2half_rn(stage2[jj + 1][il * 64 + b]);
                *(__half2*)&g_hist[(size_t)t * HB + (size_t)b * Hn + j0 + jj] = hv;
            }
        }
        __syncthreads();
    }
}

// ---------------------------------------------------------------------------
// persistent loop: 255 steps, t = 2,4,...,510 (R15, minus one redundant sync)
// ---------------------------------------------------------------------------
__global__ __launch_bounds__(NTHR, 1) void loop_kernel() {
    extern __shared__ char smem[];
    const uint32_t sb = smem_u32(smem);
    const int tid = threadIdx.x;
    const int wid = tid >> 5, lane = tid & 31;
    const int cta = blockIdx.x;
    const int jt = cta / KSPLIT, kq = cta % KSPLIT;
    const int j0 = jt * 128;
    const int ku = slice_units(kq);
    const int ku2 = ku * 2;
    const int kbase = slice_start16(kq) * 16;
    const int rc = cta * 16;

    const int mg = wid >> 1;
    const int nh = wid & 1;
    const int g8 = lane >> 2, tg = lane & 3;

    const int jl = (tid * 2) >> 6;
    const int bb = (tid * 2) & 63;
    const size_t ownIdx = (size_t)(rc + jl) * Bn + bb;

    for (int p = 0; p < 8; p++) {
        int f = tid + p * 512;
        int r = f >> 5, c = f & 31;
        if (c < ku2)
            *(uint4*)(smem + OFF_WH + r * ROWB + c * 16) =
                *(const uint4*)&g_M2[(size_t)(j0 + r) * Hn + kbase + c * 8];
    }
    __syncthreads();

    const uint32_t aLane =
        sb + OFF_WH + (uint32_t)(mg * 32 + (lane & 15)) * ROWB + (lane >> 4) * 16;
    const uint32_t bLane =
        sb + OFF_BH + (uint32_t)(nh * 32 + (lane & 7) + ((lane >> 4) & 1) * 8) * ROWB +
        ((lane >> 3) & 1) * 16;
    float (*stage)[66] = (float (*)[66])(smem + OFF_STG);

    for (int t = 2; t <= 510; t += 2) {
        const __half* hb = g_hist + (size_t)(t - 2) * HB;
        #pragma unroll
        for (int p = 0; p < 4; p++) {
            int f = tid + p * 512;
            int b = f >> 5, c = f & 31;
            if (c < ku2)
                *(uint4*)(smem + OFF_BH + b * ROWB + c * 16) =
                    __ldcg((const uint4*)&hb[(size_t)b * Hn + kbase + c * 8]);
        }
        __syncthreads();

        float acc[2][4][4] = {};
        if (wid < 8) {
            #pragma unroll 5
            for (int kk = 0; kk < ku; kk++) {
                uint32_t A0[4], A1[4], Bv[4], Bw[4];
                ldsm4(A0, aLane + kk * 32);
                ldsm4(A1, aLane + kk * 32 + 16 * ROWB);
                ldsm4(Bv, bLane + kk * 32);
                ldsm4(Bw, bLane + kk * 32 + 16 * ROWB);
                mma16816(acc[0][0], A0, Bv[0], Bv[1]);
                mma16816(acc[0][1], A0, Bv[2], Bv[3]);
                mma16816(acc[0][2], A0, Bw[0], Bw[1]);
                mma16816(acc[0][3], A0, Bw[2], Bw[3]);
                mma16816(acc[1][0], A1, Bv[0], Bv[1]);
                mma16816(acc[1][1], A1, Bv[2], Bv[3]);
                mma16816(acc[1][2], A1, Bw[0], Bw[1]);
                mma16816(acc[1][3], A1, Bw[2], Bw[3]);
            }
            #pragma unroll
            for (int mt = 0; mt < 2; mt++)
                #pragma unroll
                for (int nt = 0; nt < 4; nt++) {
                    int r0 = mt * 16 + g8, cc = nt * 8 + tg * 2;
                    int j = j0 + mg * 32 + r0;
                    int bc = nh * 32 + cc;
                    __stcg((float2*)&g_part[((size_t)kq * Hn + j) * Bn + bc],
                           make_float2(acc[mt][nt][0], acc[mt][nt][1]));
                    __stcg((float2*)&g_part[((size_t)kq * Hn + j + 8) * Bn + bc],
                           make_float2(acc[mt][nt][2], acc[mt][nt][3]));
                }
        }

        float2 vv = make_float2(0.f, 0.f);
        if (cta < 128)
            vv = *(const float2*)&g_V[(size_t)((t >> 1) - 1) * HB + ownIdx];

        grid_sync_dev();

        if (cta < 128) {
            float2 s = vv;
            #pragma unroll
            for (int q = 0; q < KSPLIT; q++) {
                float2 v = __ldcg((const float2*)&g_part[(size_t)q * HB + ownIdx]);
                s.x += v.x; s.y += v.y;
            }
            *(float2*)&stage[jl][bb] = s;
            __syncthreads();
            int b = tid >> 3, kk = tid & 7;
            __half2 hv;
            hv.x = __float2half_rn(stage[kk * 2][b]);
            hv.y = __float2half_rn(stage[kk * 2 + 1][b]);
            *(__half2*)&g_hist[(size_t)t * HB + (size_t)b * Hn + rc + kk * 2] = hv;
        }

        grid_sync_dev();
    }
}

// ---------------------------------------------------------------------------
// out[b][t][o] = sum_k g_hist[t][b][k] * woT[o][k]
// ---------------------------------------------------------------------------
__global__ __launch_bounds__(256) void out_kernel(float* __restrict__ out) {
    extern __shared__ char sm[];
    const uint32_t sb = smem_u32(sm);
    const int t = blockIdx.x, tid = threadIdx.x;
    const int wid = tid >> 5, lane = tid & 31;
    const int mg = wid >> 2, nh = wid & 3;

    const uint32_t aLane = (uint32_t)(mg * 32 + (lane & 15)) * GRB + (lane >> 4) * 16;
    const uint32_t bLane =
        (uint32_t)(nh * 32 + (lane & 7) + ((lane >> 4) & 1) * 8) * GRB +
        ((lane >> 3) & 1) * 16;
    const int g8 = lane >> 2, tg = lane & 3;

    float acc[2][4][4] = {};
    const __half* hsrc = g_hist + (size_t)t * HB;

    for (int k0 = 0; k0 < Hn; k0 += 128) {
        #pragma unroll
        for (int p = 0; p < 4; p++) {
            int f = tid + p * 256;
            int r = f >> 4, c = f & 15;
            *(uint4*)(sm + r * GRB + c * 16) =
                *(const uint4*)&hsrc[(size_t)r * Hn + k0 + c * 8];
        }
        #pragma unroll
        for (int p = 0; p < 8; p++) {
            int f = tid + p * 256;
            int r = f >> 4, c = f & 15;
            *(uint4*)(sm + OFF_OB + r * GRB + c * 16) =
                *(const uint4*)&g_woT[(size_t)r * Hn + k0 + c * 8];
        }
        __syncthreads();
        const uint32_t aB = sb + aLane, bB = sb + OFF_OB + bLane;
        #pragma unroll
        for (int kk = 0; kk < 8; kk++) {
            uint32_t A0[4], A1[4], Bv[4], Bw[4];
            ldsm4(A0, aB + kk * 32);
            ldsm4(A1, aB + kk * 32 + 16 * GRB);
            ldsm4(Bv, bB + kk * 32);
            ldsm4(Bw, bB + kk * 32 + 16 * GRB);
            mma16816(acc[0][0], A0, Bv[0], Bv[1]);
            mma16816(acc[0][1], A0, Bv[2], Bv[3]);
            mma16816(acc[0][2], A0, Bw[0], Bw[1]);
            mma16816(acc[0][3], A0, Bw[2], Bw[3]);
            mma16816(acc[1][0], A1, Bv[0], Bv[1]);
            mma16816(acc[1][1], A1, Bv[2], Bv[3]);
            mma16816(acc[1][2], A1, Bw[0], Bw[1]);
            mma16816(acc[1][3], A1, Bw[2], Bw[3]);
        }
        __syncthreads();
    }

    #pragma unroll
    for (int mt = 0; mt < 2; mt++)
        #pragma unroll
        for (int nt = 0; nt < 4; nt++) {
            int r0 = mt * 16 + g8, cc = nt * 8 + tg * 2;
            int b = mg * 32 + r0;
            int o = nh * 32 + cc;
            *(float2*)&out[((size_t)b * Sn + t) * On + o] =
                make_float2(acc[mt][nt][0], acc[mt][nt][1]);
            *(float2*)&out[((size_t)(b + 8) * Sn + t) * On + o] =
                make_float2(acc[mt][nt][2], acc[mt][nt][3]);
        }
}

// ---------------------------------------------------------------------------
extern "C" void kernel_launch(void* const* d_in, const int* in_sizes, int n_in,
                              void* d_out, int out_size) {
    const float* x     = (const float*)d_in[0];
    const float* noise = (const float*)d_in[1];
    const float* wi    = (const float*)d_in[2];
    const float* wrec  = (const float*)d_in[3];
    const float* wout  = (const float*)d_in[4];
    const float* g     = (const float*)d_in[5];
    const float* h0    = (const float*)d_in[6];
    float* out = (float*)d_out;

    cudaFuncSetAttribute(loop_kernel, cudaFuncAttributeMaxDynamicSharedMemorySize,
                         SMEM_TOTAL);
    cudaFuncSetAttribute(u_kernel, cudaFuncAttributeMaxDynamicSharedMemorySize, USMEM);
    cudaFuncSetAttribute(out_kernel, cudaFuncAttributeMaxDynamicSharedMemorySize, OSMEM);
    cudaFuncSetAttribute(mm2_kernel, cudaFuncAttributeMaxDynamicSharedMemorySize,
                         MM2_SMEM);
    cudaFuncSetAttribute(v_kernel, cudaFuncAttributeMaxDynamicSharedMemorySize, V2_SMEM);
    cudaFuncSetAttribute(odd_kernel, cudaFuncAttributeMaxDynamicSharedMemorySize,
                         V2_SMEM);

    mprep_kernel<<<dim3(Hn / 32, Hn / 32), dim3(32, 32)>>>(wrec, g);
    wtprep_kernel<<<dim3(Hn / 32, On / 32), dim3(32, 32)>>>(wout);
    witprep_kernel<<<dim3(In / 32, Hn / 32), dim3(32, 32)>>>(wi);
    xhprep_kernel<<<Bn * Sn * In / 256, 256>>>(x);
    hbinit_kernel<<<HB / 256, 256>>>(h0);
    u_kernel<<<dim3(Hn / 128, 128), 256, USMEM>>>(noise);
    mm2_kernel<<<dim3(16, 16), 512, MM2_SMEM>>>();
    v_kernel<<<dim3(16, 64), 512, V2_SMEM>>>();
    loop_kernel<<<NCTA, NTHR, SMEM_TOTAL>>>();
    odd_kernel<<<dim3(16, 64), 512, V2_SMEM>>>();
    out_kernel<<<Sn, 256, OSMEM>>>(out);
}

// round 17
// speedup vs baseline: 1.5730x; 1.0641x over previous
#include <cuda_runtime.h>
#include <cuda_fp16.h>
#include <cstdint>
#include <cstddef>

// ---------------------------------------------------------------------------
// RNN_fish, R17: step-doubled persistent HMMA kernel + odd-state folding:
//   h_{2i} = M^2 h_{2i-2} + V_i           (sequential loop, 255 steps)
//   out_{2i}   = h_{2i} @ wout            (out_kernel, even t)
//   out_{2i+1} = h_{2i} @ Wm + alpha*x@Wxo + 0.005*n@wout   (oddout_kernel)
//   Wm = M^T wout (hi+lo fp16, effectively exact), Wxo = wi@wout
// odd_kernel deleted entirely.
// ---------------------------------------------------------------------------

namespace {
constexpr int Bn = 64;
constexpr int Sn = 512;
constexpr int In = 128;
constexpr int Hn = 2048;
constexpr int On = 128;
constexpr int KSPLIT = 9;
constexpr int NCTA = 144;
constexpr int NTHR = 512;
constexpr int HB = Hn * Bn;
constexpr float kNoise = 0.005f;
constexpr float kAlpha = 0.2f;
constexpr float kLoInv = 1.0f / 4096.0f;

__host__ __device__ __forceinline__ int slice_units(int kq) { return 14 + (kq < 2); }
__host__ __device__ __forceinline__ int slice_start16(int kq) {
    return kq * 14 + (kq < 2 ? kq : 2);
}

// loop smem
constexpr int ROWB = 528;
constexpr int OFF_WH = 0;
constexpr int OFF_BH = OFF_WH + 128 * ROWB;
constexpr int OFF_STG = OFF_BH;
constexpr int SMEM_TOTAL = OFF_BH + 64 * ROWB;  // 101376

// generic 128-wide GEMM smem
constexpr int GRB = 272;
constexpr int GA = 128 * GRB;                   // 34816
constexpr int MM2_SMEM = 4 * GA;                // 139264 (also wmprep)
constexpr int V2_SMEM = GA + 256 * GRB;         // 104448
// u-kernel
constexpr int UOFF_BH = 64 * GRB;
constexpr int UOFF_BL = UOFF_BH + 128 * GRB;
constexpr int UOFF_ST = UOFF_BL + 128 * GRB;
constexpr int USMEM = UOFF_ST + 64 * 132 * 4;   // 120832
// out-kernel
constexpr int OFF_OB = 64 * GRB;
constexpr int OSMEM = OFF_OB + 128 * GRB;       // 52224
// oddout kernel: A_h(64) + A_n(64) + WmH(128) + WmL(128) + wo(128)
constexpr int OO_AH = 0;
constexpr int OO_AN = 64 * GRB;                 // 17408
constexpr int OO_WMH = 128 * GRB;               // 34816
constexpr int OO_WML = OO_WMH + GA;             // 69632
constexpr int OO_WO = OO_WML + GA;              // 104448
constexpr int OODD_SMEM = OO_WO + GA;           // 139264
}

// device globals
__device__ float g_U[(size_t)Sn * Hn * Bn];          // [t][j][b] fp32 (even t>=2)
__device__ float g_V[(size_t)255 * Hn * Bn];         // [i][j][b] fp32
__device__ float g_part[(size_t)KSPLIT * Hn * Bn];   // [q][j][b]
__device__ __half g_Mh[(size_t)Hn * Hn];             // [j][k]
__device__ __half g_Ml[(size_t)Hn * Hn];
__device__ __half g_MTh[(size_t)Hn * Hn];            // [k][j]
__device__ __half g_MTl[(size_t)Hn * Hn];
__device__ __half g_M2[(size_t)Hn * Hn];             // [j][k] fp16 M^2
__device__ __half g_hist[(size_t)Sn * Bn * Hn];      // [t][b][k] fp16 (even t)
__device__ __half g_Uo[(size_t)256 * Bn * Hn];       // [(t-1)/2][b][k] fp16, odd t
__device__ __half g_woT[(size_t)On * Hn];            // [o][k] fp16 hi of wout^T
__device__ __half g_woTl[(size_t)On * Hn];           // [o][k] 4096*lo
__device__ __half g_WmTh[(size_t)On * Hn];           // [o][k] hi of (M^T wout)^T
__device__ __half g_WmTl[(size_t)On * Hn];           // [o][k] 4096*lo
__device__ __half g_WxoTh[(size_t)On * In];          // [o][i] hi of (alpha*wi@wout)^T
__device__ __half g_WxoTl[(size_t)On * In];          // [o][i] 4096*lo
__device__ __half g_wiTh[(size_t)Hn * In];
__device__ __half g_wiTl[(size_t)Hn * In];
__device__ __half g_xh[(size_t)Bn * Sn * In];        // [b][t][i]
__device__ unsigned g_bar_count;
__device__ unsigned g_bar_gen;

// ---- helpers ----
__device__ __forceinline__ uint32_t smem_u32(const void* p) {
    uint32_t a;
    asm("{ .reg .u64 t; cvta.to.shared.u64 t, %1; cvt.u32.u64 %0, t; }" : "=r"(a) : "l"(p));
    return a;
}
__device__ __forceinline__ void ldsm4(uint32_t a[4], uint32_t addr) {
    asm volatile("ldmatrix.sync.aligned.m8n8.x4.shared.b16 {%0,%1,%2,%3}, [%4];"
                 : "=r"(a[0]), "=r"(a[1]), "=r"(a[2]), "=r"(a[3]) : "r"(addr));
}
__device__ __forceinline__ void mma16816(float c[4], const uint32_t a[4],
                                         uint32_t b0, uint32_t b1) {
    asm volatile("mma.sync.aligned.m16n8k16.row.col.f32.f16.f16.f32 "
                 "{%0,%1,%2,%3}, {%4,%5,%6,%7}, {%8,%9}, {%0,%1,%2,%3};"
                 : "+f"(c[0]), "+f"(c[1]), "+f"(c[2]), "+f"(c[3])
                 : "r"(a[0]), "r"(a[1]), "r"(a[2]), "r"(a[3]), "r"(b0), "r"(b1));
}

// flat grid barrier (proven)
__device__ __forceinline__ void grid_sync_dev() {
    __syncthreads();
    if (threadIdx.x == 0) {
        __threadfence();
        unsigned old, my;
        asm volatile("ld.acquire.gpu.global.u32 %0, [%1];"
                     : "=r"(old) : "l"(&g_bar_gen) : "memory");
        asm volatile("atom.release.gpu.global.add.u32 %0, [%1], %2;"
                     : "=r"(my) : "l"(&g_bar_count), "r"(1u) : "memory");
        if (my == (unsigned)(NCTA - 1)) {
            asm volatile("st.global.u32 [%0], %1;" :: "l"(&g_bar_count), "r"(0u) : "memory");
            asm volatile("red.release.gpu.global.add.u32 [%0], %1;"
                         :: "l"(&g_bar_gen), "r"(1u) : "memory");
        } else {
            unsigned cur;
            do {
                asm volatile("ld.acquire.gpu.global.u32 %0, [%1];"
                             : "=r"(cur) : "l"(&g_bar_gen) : "memory");
            } while (cur == old);
        }
        __threadfence();
    }
    __syncthreads();
}

// ---------------------------------------------------------------------------
// prep kernels
// ---------------------------------------------------------------------------
__global__ __launch_bounds__(1024) void mprep_kernel(const float* __restrict__ wrec,
                                                     const float* __restrict__ g) {
    __shared__ float sh[32][33], sl[32][33];
    int tx = threadIdx.x, ty = threadIdx.y;
    int j0 = blockIdx.y * 32, k0 = blockIdx.x * 32;
    int j = j0 + ty, k = k0 + tx;
    float v = kAlpha * g[k] * wrec[(size_t)j * Hn + k];
    if (j == k) v += 1.0f - kAlpha;
    __half hi = __float2half_rn(v);
    float lo = (v - __half2float(hi)) * 4096.0f;
    g_Mh[(size_t)j * Hn + k] = hi;
    g_Ml[(size_t)j * Hn + k] = __float2half_rn(lo);
    sh[ty][tx] = __half2float(hi);
    sl[ty][tx] = lo;
    __syncthreads();
    g_MTh[(size_t)(k0 + ty) * Hn + j0 + tx] = __float2half_rn(sh[tx][ty]);
    g_MTl[(size_t)(k0 + ty) * Hn + j0 + tx] = __float2half_rn(sl[tx][ty]);
}

__global__ void hbinit_kernel(const float* __restrict__ h0) {
    int n = blockIdx.x * blockDim.x + threadIdx.x;
    g_hist[n] = __float2half_rn(h0[n & (Hn - 1)]);
}

__global__ void xhprep_kernel(const float* __restrict__ x) {
    int n = blockIdx.x * blockDim.x + threadIdx.x;
    g_xh[n] = __float2half_rn(x[n]);
}

__global__ __launch_bounds__(1024) void wtprep_kernel(const float* __restrict__ wout) {
    __shared__ float s[32][33];
    int tx = threadIdx.x, ty = threadIdx.y;
    int k0 = blockIdx.x * 32, o0 = blockIdx.y * 32;
    s[ty][tx] = wout[(size_t)(k0 + ty) * On + o0 + tx];
    __syncthreads();
    float v = s[tx][ty];
    __half hi = __float2half_rn(v);
    g_woT[(size_t)(o0 + ty) * Hn + k0 + tx] = hi;
    g_woTl[(size_t)(o0 + ty) * Hn + k0 + tx] =
        __float2half_rn((v - __half2float(hi)) * 4096.0f);
}

__global__ __launch_bounds__(1024) void witprep_kernel(const float* __restrict__ wi) {
    __shared__ float s[32][33];
    int tx = threadIdx.x, ty = threadIdx.y;
    int i0 = blockIdx.x * 32, j0 = blockIdx.y * 32;
    s[ty][tx] = wi[(size_t)(i0 + ty) * Hn + j0 + tx];
    __syncthreads();
    float v = s[tx][ty];
    __half hi = __float2half_rn(v);
    g_wiTh[(size_t)(j0 + ty) * In + i0 + tx] = hi;
    g_wiTl[(size_t)(j0 + ty) * In + i0 + tx] =
        __float2half_rn((v - __half2float(hi)) * 4096.0f);
}

// Wxo = alpha * wi @ wout, transposed hi/lo fp16 [o][i]
__global__ __launch_bounds__(128) void wxoprep_kernel(const float* __restrict__ wi,
                                                      const float* __restrict__ wout) {
    int i = blockIdx.x, o = threadIdx.x;
    float s0 = 0.f, s1 = 0.f, s2 = 0.f, s3 = 0.f;
    for (int j = 0; j < Hn; j += 4) {
        s0 = fmaf(wi[(size_t)i * Hn + j],     wout[(size_t)j * On + o],       s0);
        s1 = fmaf(wi[(size_t)i * Hn + j + 1], wout[(size_t)(j + 1) * On + o], s1);
        s2 = fmaf(wi[(size_t)i * Hn + j + 2], wout[(size_t)(j + 2) * On + o], s2);
        s3 = fmaf(wi[(size_t)i * Hn + j + 3], wout[(size_t)(j + 3) * On + o], s3);
    }
    float v = kAlpha * ((s0 + s1) + (s2 + s3));
    __half hi = __float2half_rn(v);
    g_WxoTh[(size_t)o * In + i] = hi;
    g_WxoTl[(size_t)o * In + i] = __float2half_rn((v - __half2float(hi)) * 4096.0f);
}

// ---------------------------------------------------------------------------
// wmprep: Wm[k][o] = sum_j MT[k][j] * wout[j][o]; 3 chains (hh + hl + lh)
// stored transposed hi/lo: g_WmT{h,l}[o][k]. Grid (16,1), 512 thr.
// ---------------------------------------------------------------------------
__global__ __launch_bounds__(512) void wmprep_kernel() {
    extern __shared__ char sm[];
    const uint32_t sb = smem_u32(sm);
    const int k0 = blockIdx.x * 128;
    const int tid = threadIdx.x;
    const int wid = tid >> 5, lane = tid & 31;
    const int mg = wid >> 2, nh = wid & 3;
    const int g8 = lane >> 2, tg = lane & 3;

    const uint32_t aOff = (uint32_t)(mg * 32 + (lane & 15)) * GRB + (lane >> 4) * 16;
    const uint32_t bOff =
        (uint32_t)(nh * 32 + (lane & 7) + ((lane >> 4) & 1) * 8) * GRB +
        ((lane >> 3) & 1) * 16;

    float a1[2][4][4] = {}, a2[2][4][4] = {};
    for (int m0 = 0; m0 < Hn; m0 += 128) {
        #pragma unroll
        for (int p = 0; p < 4; p++) {
            int f = tid + p * 512;
            int r = f >> 4, c = f & 15;
            size_t ga = (size_t)(k0 + r) * Hn + m0 + c * 8;
            size_t gb = (size_t)r * Hn + m0 + c * 8;
            *(uint4*)(sm + 0 * GA + r * GRB + c * 16) = *(const uint4*)&g_MTh[ga];
            *(uint4*)(sm + 1 * GA + r * GRB + c * 16) = *(const uint4*)&g_MTl[ga];
            *(uint4*)(sm + 2 * GA + r * GRB + c * 16) = *(const uint4*)&g_woT[gb];
            *(uint4*)(sm + 3 * GA + r * GRB + c * 16) = *(const uint4*)&g_woTl[gb];
        }
        __syncthreads();
        #pragma unroll
        for (int kk = 0; kk < 8; kk++) {
            uint32_t Ah0[4], Ah1[4], Al0[4], Al1[4], Bh0[4], Bh1[4], Bl0[4], Bl1[4];
            ldsm4(Ah0, sb + 0 * GA + aOff + kk * 32);
            ldsm4(Ah1, sb + 0 * GA + aOff + kk * 32 + 16 * GRB);
            ldsm4(Al0, sb + 1 * GA + aOff + kk * 32);
            ldsm4(Al1, sb + 1 * GA + aOff + kk * 32 + 16 * GRB);
            ldsm4(Bh0, sb + 2 * GA + bOff + kk * 32);
            ldsm4(Bh1, sb + 2 * GA + bOff + kk * 32 + 16 * GRB);
            ldsm4(Bl0, sb + 3 * GA + bOff + kk * 32);
            ldsm4(Bl1, sb + 3 * GA + bOff + kk * 32 + 16 * GRB);
            mma16816(a1[0][0], Ah0, Bh0[0], Bh0[1]); mma16816(a1[0][1], Ah0, Bh0[2], Bh0[3]);
            mma16816(a1[0][2], Ah0, Bh1[0], Bh1[1]); mma16816(a1[0][3], Ah0, Bh1[2], Bh1[3]);
            mma16816(a1[1][0], Ah1, Bh0[0], Bh0[1]); mma16816(a1[1][1], Ah1, Bh0[2], Bh0[3]);
            mma16816(a1[1][2], Ah1, Bh1[0], Bh1[1]); mma16816(a1[1][3], Ah1, Bh1[2], Bh1[3]);
            mma16816(a2[0][0], Ah0, Bl0[0], Bl0[1]); mma16816(a2[0][1], Ah0, Bl0[2], Bl0[3]);
            mma16816(a2[0][2], Ah0, Bl1[0], Bl1[1]); mma16816(a2[0][3], Ah0, Bl1[2], Bl1[3]);
            mma16816(a2[1][0], Ah1, Bl0[0], Bl0[1]); mma16816(a2[1][1], Ah1, Bl0[2], Bl0[3]);
            mma16816(a2[1][2], Ah1, Bl1[0], Bl1[1]); mma16816(a2[1][3], Ah1, Bl1[2], Bl1[3]);
            mma16816(a2[0][0], Al0, Bh0[0], Bh0[1]); mma16816(a2[0][1], Al0, Bh0[2], Bh0[3]);
            mma16816(a2[0][2], Al0, Bh1[0], Bh1[1]); mma16816(a2[0][3], Al0, Bh1[2], Bh1[3]);
            mma16816(a2[1][0], Al1, Bh0[0], Bh0[1]); mma16816(a2[1][1], Al1, Bh0[2], Bh0[3]);
            mma16816(a2[1][2], Al1, Bh1[0], Bh1[1]); mma16816(a2[1][3], Al1, Bh1[2], Bh1[3]);
        }
        __syncthreads();
    }
    #pragma unroll
    for (int mt = 0; mt < 2; mt++)
        #pragma unroll
        for (int nt = 0; nt < 4; nt++) {
            int krow = k0 + mg * 32 + mt * 16 + g8;
            int o = nh * 32 + nt * 8 + tg * 2;
            #pragma unroll
            for (int e = 0; e < 4; e++) {
                int kk = krow + (e >> 1) * 8;
                int oo = o + (e & 1);
                float v = fmaf(kLoInv, a2[mt][nt][e], a1[mt][nt][e]);
                __half hi = __float2half_rn(v);
                g_WmTh[(size_t)oo * Hn + kk] = hi;
                g_WmTl[(size_t)oo * Hn + kk] =
                    __float2half_rn((v - __half2float(hi)) * 4096.0f);
            }
        }
}

// ---------------------------------------------------------------------------
// u_kernel: 4 t's per CTA, wiT resident. Even t -> g_U fp32; odd t -> g_Uo fp16.
// ---------------------------------------------------------------------------
__global__ __launch_bounds__(256) void u_kernel(const float* __restrict__ noise) {
    extern __shared__ char sm[];
    const uint32_t sb = smem_u32(sm);
    const int jt = blockIdx.x;
    const int j0 = jt * 128;
    const int tid = threadIdx.x;
    const int wid = tid >> 5, lane = tid & 31;
    const int mgb = wid >> 2, njw = wid & 3;
    const int g8 = lane >> 2, tg = lane & 3;

    #pragma unroll
    for (int p = 0; p < 8; p++) {
        int f = tid + p * 256;
        int r = f >> 4, c = f & 15;
        size_t gi = (size_t)(j0 + r) * In + c * 8;
        *(uint4*)(sm + UOFF_BH + r * GRB + c * 16) = *(const uint4*)&g_wiTh[gi];
        *(uint4*)(sm + UOFF_BL + r * GRB + c * 16) = *(const uint4*)&g_wiTl[gi];
    }

    const uint32_t aLane =
        sb + (uint32_t)(mgb * 32 + (lane & 15)) * GRB + (lane >> 4) * 16;
    const uint32_t bLane =
        (uint32_t)(njw * 32 + (lane & 7) + ((lane >> 4) & 1) * 8) * GRB +
        ((lane >> 3) & 1) * 16;
    float (*stage)[132] = (float (*)[132])(sm + UOFF_ST);

    for (int r4 = 0; r4 < 4; r4++) {
        int t = blockIdx.y * 4 + 1 + r4;
        if (t >= Sn) break;

        #pragma unroll
        for (int p = 0; p < 4; p++) {
            int f = tid + p * 256;
            int r = f >> 4, c = f & 15;
            *(uint4*)(sm + r * GRB + c * 16) =
                *(const uint4*)&g_xh[((size_t)r * Sn + (t - 1)) * In + c * 8];
        }
        __syncthreads();

        float a1[2][4][4] = {}, a2[2][4][4] = {};
        #pragma unroll
        for (int kk = 0; kk < 8; kk++) {
            uint32_t A0[4], A1[4], Bv[4], Bw[4];
            ldsm4(A0, aLane + kk * 32);
            ldsm4(A1, aLane + kk * 32 + 16 * GRB);
            ldsm4(Bv, sb + UOFF_BH + bLane + kk * 32);
            ldsm4(Bw, sb + UOFF_BH + bLane + kk * 32 + 16 * GRB);
            mma16816(a1[0][0], A0, Bv[0], Bv[1]); mma16816(a1[0][1], A0, Bv[2], Bv[3]);
            mma16816(a1[0][2], A0, Bw[0], Bw[1]); mma16816(a1[0][3], A0, Bw[2], Bw[3]);
            mma16816(a1[1][0], A1, Bv[0], Bv[1]); mma16816(a1[1][1], A1, Bv[2], Bv[3]);
            mma16816(a1[1][2], A1, Bw[0], Bw[1]); mma16816(a1[1][3], A1, Bw[2], Bw[3]);
            ldsm4(Bv, sb + UOFF_BL + bLane + kk * 32);
            ldsm4(Bw, sb + UOFF_BL + bLane + kk * 32 + 16 * GRB);
            mma16816(a2[0][0], A0, Bv[0], Bv[1]); mma16816(a2[0][1], A0, Bv[2], Bv[3]);
            mma16816(a2[0][2], A0, Bw[0], Bw[1]); mma16816(a2[0][3], A0, Bw[2], Bw[3]);
            mma16816(a2[1][0], A1, Bv[0], Bv[1]); mma16816(a2[1][1], A1, Bv[2], Bv[3]);
            mma16816(a2[1][2], A1, Bw[0], Bw[1]); mma16816(a2[1][3], A1, Bw[2], Bw[3]);
        }
        __syncthreads();

        #pragma unroll
        for (int mt = 0; mt < 2; mt++)
            #pragma unroll
            for (int nt = 0; nt < 4; nt++) {
                int rb = mgb * 32 + mt * 16 + g8;
                int jc = njw * 32 + nt * 8 + tg * 2;
                stage[rb][jc]     = fmaf(kLoInv, a2[mt][nt][0], a1[mt][nt][0]);
                stage[rb][jc + 1] = fmaf(kLoInv, a2[mt][nt][1], a1[mt][nt][1]);
                stage[rb + 8][jc]     = fmaf(kLoInv, a2[mt][nt][2], a1[mt][nt][2]);
                stage[rb + 8][jc + 1] = fmaf(kLoInv, a2[mt][nt][3], a1[mt][nt][3]);
            }
        __syncthreads();

        #pragma unroll
        for (int rep = 0; rep < 8; rep++) {
            int b = wid * 8 + rep;
            #pragma unroll
            for (int c = 0; c < 4; c++) {
                int j = c * 32 + lane;
                float nv = noise[((size_t)b * Sn + (t - 1)) * Hn + j0 + j];
                stage[b][j] = fmaf(kAlpha, stage[b][j], kNoise * nv);
            }
        }
        __syncthreads();

        if (!(t & 1)) {   // fp32 [j][b] store (even t only; odd fp32 unused)
            int j = tid >> 1, bh = (tid & 1) * 32;
            #pragma unroll
            for (int bc = 0; bc < 8; bc++) {
                int b0 = bh + bc * 4;
                float4 v = make_float4(stage[b0][j], stage[b0 + 1][j],
                                       stage[b0 + 2][j], stage[b0 + 3][j]);
                *(float4*)&g_U[((size_t)t * Hn + j0 + j) * Bn + b0] = v;
            }
        } else {          // fp16 [b][k] store for odd t (feeds v_kernel)
            int ui = (t - 1) >> 1;
            int b = tid >> 2;
            #pragma unroll
            for (int p = 0; p < 16; p++) {
                int jj = (tid & 3) * 2 + p * 8;
                __half2 hv;
                hv.x = __float2half_rn(stage[b][jj]);
                hv.y = __float2half_rn(stage[b][jj + 1]);
                *(__half2*)&g_Uo[(size_t)ui * HB + (size_t)b * Hn + j0 + jj] = hv;
            }
        }
        __syncthreads();
    }
}

// ---------------------------------------------------------------------------
// mm2_kernel: M2 = M*M, 3 chains (unchanged)
// ---------------------------------------------------------------------------
__global__ __launch_bounds__(512) void mm2_kernel() {
    extern __shared__ char sm[];
    const uint32_t sb = smem_u32(sm);
    const int j0 = blockIdx.x * 128, k0 = blockIdx.y * 128;
    const int tid = threadIdx.x;
    const int wid = tid >> 5, lane = tid & 31;
    const int mg = wid >> 2, nh = wid & 3;
    const int g8 = lane >> 2, tg = lane & 3;

    const uint32_t aOff = (uint32_t)(mg * 32 + (lane & 15)) * GRB + (lane >> 4) * 16;
    const uint32_t bOff =
        (uint32_t)(nh * 32 + (lane & 7) + ((lane >> 4) & 1) * 8) * GRB +
        ((lane >> 3) & 1) * 16;

    float a1[2][4][4] = {}, a2[2][4][4] = {};
    for (int m0 = 0; m0 < Hn; m0 += 128) {
        #pragma unroll
        for (int p = 0; p < 4; p++) {
            int f = tid + p * 512;
            int r = f >> 4, c = f & 15;
            size_t ga = (size_t)(j0 + r) * Hn + m0 + c * 8;
            size_t gb = (size_t)(k0 + r) * Hn + m0 + c * 8;
            *(uint4*)(sm + 0 * GA + r * GRB + c * 16) = *(const uint4*)&g_Mh[ga];
            *(uint4*)(sm + 1 * GA + r * GRB + c * 16) = *(const uint4*)&g_Ml[ga];
            *(uint4*)(sm + 2 * GA + r * GRB + c * 16) = *(const uint4*)&g_MTh[gb];
            *(uint4*)(sm + 3 * GA + r * GRB + c * 16) = *(const uint4*)&g_MTl[gb];
        }
        __syncthreads();
        #pragma unroll
        for (int kk = 0; kk < 8; kk++) {
            uint32_t Ah0[4], Ah1[4], Al0[4], Al1[4], Bh0[4], Bh1[4], Bl0[4], Bl1[4];
            ldsm4(Ah0, sb + 0 * GA + aOff + kk * 32);
            ldsm4(Ah1, sb + 0 * GA + aOff + kk * 32 + 16 * GRB);
            ldsm4(Al0, sb + 1 * GA + aOff + kk * 32);
            ldsm4(Al1, sb + 1 * GA + aOff + kk * 32 + 16 * GRB);
            ldsm4(Bh0, sb + 2 * GA + bOff + kk * 32);
            ldsm4(Bh1, sb + 2 * GA + bOff + kk * 32 + 16 * GRB);
            ldsm4(Bl0, sb + 3 * GA + bOff + kk * 32);
            ldsm4(Bl1, sb + 3 * GA + bOff + kk * 32 + 16 * GRB);
            mma16816(a1[0][0], Ah0, Bh0[0], Bh0[1]); mma16816(a1[0][1], Ah0, Bh0[2], Bh0[3]);
            mma16816(a1[0][2], Ah0, Bh1[0], Bh1[1]); mma16816(a1[0][3], Ah0, Bh1[2], Bh1[3]);
            mma16816(a1[1][0], Ah1, Bh0[0], Bh0[1]); mma16816(a1[1][1], Ah1, Bh0[2], Bh0[3]);
            mma16816(a1[1][2], Ah1, Bh1[0], Bh1[1]); mma16816(a1[1][3], Ah1, Bh1[2], Bh1[3]);
            mma16816(a2[0][0], Ah0, Bl0[0], Bl0[1]); mma16816(a2[0][1], Ah0, Bl0[2], Bl0[3]);
            mma16816(a2[0][2], Ah0, Bl1[0], Bl1[1]); mma16816(a2[0][3], Ah0, Bl1[2], Bl1[3]);
            mma16816(a2[1][0], Ah1, Bl0[0], Bl0[1]); mma16816(a2[1][1], Ah1, Bl0[2], Bl0[3]);
            mma16816(a2[1][2], Ah1, Bl1[0], Bl1[1]); mma16816(a2[1][3], Ah1, Bl1[2], Bl1[3]);
            mma16816(a2[0][0], Al0, Bh0[0], Bh0[1]); mma16816(a2[0][1], Al0, Bh0[2], Bh0[3]);
            mma16816(a2[0][2], Al0, Bh1[0], Bh1[1]); mma16816(a2[0][3], Al0, Bh1[2], Bh1[3]);
            mma16816(a2[1][0], Al1, Bh0[0], Bh0[1]); mma16816(a2[1][1], Al1, Bh0[2], Bh0[3]);
            mma16816(a2[1][2], Al1, Bh1[0], Bh1[1]); mma16816(a2[1][3], Al1, Bh1[2], Bh1[3]);
        }
        __syncthreads();
    }
    #pragma unroll
    for (int mt = 0; mt < 2; mt++)
        #pragma unroll
        for (int nt = 0; nt < 4; nt++) {
            int j = j0 + mg * 32 + mt * 16 + g8;
            int k = k0 + nh * 32 + nt * 8 + tg * 2;
            __half2 v0, v1;
            v0.x = __float2half_rn(fmaf(kLoInv, a2[mt][nt][0], a1[mt][nt][0]));
            v0.y = __float2half_rn(fmaf(kLoInv, a2[mt][nt][1], a1[mt][nt][1]));
            v1.x = __float2half_rn(fmaf(kLoInv, a2[mt][nt][2], a1[mt][nt][2]));
            v1.y = __float2half_rn(fmaf(kLoInv, a2[mt][nt][3], a1[mt][nt][3]));
            *(__half2*)&g_M2[(size_t)j * Hn + k] = v0;
            *(__half2*)&g_M2[(size_t)(j + 8) * Hn + k] = v1;
        }
}

// ---------------------------------------------------------------------------
// v_kernel: V[i][j][b] = sum_k Mh[j][k]*Uo[i][b][k] + U[2i+2][j][b]  (unchanged)
// ---------------------------------------------------------------------------
__global__ __launch_bounds__(512) void v_kernel() {
    extern __shared__ char sm[];
    const uint32_t sb = smem_u32(sm);
    const int j0 = blockIdx.x * 128;
    const int i0 = blockIdx.y * 4;
    const int tid = threadIdx.x;
    const int wid = tid >> 5, lane = tid & 31;
    const int mg = wid >> 2, nh = wid & 3;
    const int g8 = lane >> 2, tg = lane & 3;

    const uint32_t aOff = (uint32_t)(mg * 32 + (lane & 15)) * GRB + (lane >> 4) * 16;
    const uint32_t bOff =
        (uint32_t)(nh * 32 + (lane & 7) + ((lane >> 4) & 1) * 8) * GRB +
        ((lane >> 3) & 1) * 16;

    float acc[2][2][4][4] = {};
    for (int m0 = 0; m0 < Hn; m0 += 128) {
        #pragma unroll
        for (int p = 0; p < 4; p++) {
            int f = tid + p * 512;
            int r = f >> 4, c = f & 15;
            *(uint4*)(sm + r * GRB + c * 16) =
                *(const uint4*)&g_Mh[(size_t)(j0 + r) * Hn + m0 + c * 8];
        }
        #pragma unroll
        for (int p = 0; p < 8; p++) {
            int f = tid + p * 512;
            int r = f >> 4, c = f & 15;
            int il = r >> 6, b = r & 63;
            *(uint4*)(sm + GA + r * GRB + c * 16) =
                *(const uint4*)&g_Uo[(size_t)(i0 + il) * HB + (size_t)b * Hn + m0 + c * 8];
        }
        __syncthreads();
        #pragma unroll
        for (int kk = 0; kk < 8; kk++) {
            uint32_t A0[4], A1[4];
            ldsm4(A0, sb + aOff + kk * 32);
            ldsm4(A1, sb + aOff + kk * 32 + 16 * GRB);
            #pragma unroll
            for (int hf = 0; hf < 2; hf++) {
                uint32_t Bv[4], Bw[4];
                uint32_t bb = sb + GA + hf * 128 * GRB + bOff + kk * 32;
                ldsm4(Bv, bb);
                ldsm4(Bw, bb + 16 * GRB);
                mma16816(acc[hf][0][0], A0, Bv[0], Bv[1]);
                mma16816(acc[hf][0][1], A0, Bv[2], Bv[3]);
                mma16816(acc[hf][0][2], A0, Bw[0], Bw[1]);
                mma16816(acc[hf][0][3], A0, Bw[2], Bw[3]);
                mma16816(acc[hf][1][0], A1, Bv[0], Bv[1]);
                mma16816(acc[hf][1][1], A1, Bv[2], Bv[3]);
                mma16816(acc[hf][1][2], A1, Bw[0], Bw[1]);
                mma16816(acc[hf][1][3], A1, Bw[2], Bw[3]);
            }
        }
        __syncthreads();
    }
    #pragma unroll
    for (int hf = 0; hf < 2; hf++)
        #pragma unroll
        for (int mt = 0; mt < 2; mt++)
            #pragma unroll
            for (int nt = 0; nt < 4; nt++) {
                int brow = hf * 128 + nh * 32 + nt * 8 + tg * 2;
                int i = i0 + (brow >> 6), b = brow & 63;
                if (i > 254) continue;
                int j = j0 + mg * 32 + mt * 16 + g8;
                size_t idx0 = (size_t)j * Bn + b, idx1 = (size_t)(j + 8) * Bn + b;
                float2 u0 = *(const float2*)&g_U[(size_t)(2 * i + 2) * HB + idx0];
                float2 u1 = *(const float2*)&g_U[(size_t)(2 * i + 2) * HB + idx1];
                *(float2*)&g_V[(size_t)i * HB + idx0] =
                    make_float2(acc[hf][mt][nt][0] + u0.x, acc[hf][mt][nt][1] + u0.y);
                *(float2*)&g_V[(size_t)i * HB + idx1] =
                    make_float2(acc[hf][mt][nt][2] + u1.x, acc[hf][mt][nt][3] + u1.y);
            }
}

// ---------------------------------------------------------------------------
// persistent loop: 255 steps, t = 2,4,...,510 (unchanged from R16)
// ---------------------------------------------------------------------------
__global__ __launch_bounds__(NTHR, 1) void loop_kernel() {
    extern __shared__ char smem[];
    const uint32_t sb = smem_u32(smem);
    const int tid = threadIdx.x;
    const int wid = tid >> 5, lane = tid & 31;
    const int cta = blockIdx.x;
    const int jt = cta / KSPLIT, kq = cta % KSPLIT;
    const int j0 = jt * 128;
    const int ku = slice_units(kq);
    const int ku2 = ku * 2;
    const int kbase = slice_start16(kq) * 16;
    const int rc = cta * 16;

    const int mg = wid >> 1;
    const int nh = wid & 1;
    const int g8 = lane >> 2, tg = lane & 3;

    const int jl = (tid * 2) >> 6;
    const int bb = (tid * 2) & 63;
    const size_t ownIdx = (size_t)(rc + jl) * Bn + bb;

    for (int p = 0; p < 8; p++) {
        int f = tid + p * 512;
        int r = f >> 5, c = f & 31;
        if (c < ku2)
            *(uint4*)(smem + OFF_WH + r * ROWB + c * 16) =
                *(const uint4*)&g_M2[(size_t)(j0 + r) * Hn + kbase + c * 8];
    }
    __syncthreads();

    const uint32_t aLane =
        sb + OFF_WH + (uint32_t)(mg * 32 + (lane & 15)) * ROWB + (lane >> 4) * 16;
    const uint32_t bLane =
        sb + OFF_BH + (uint32_t)(nh * 32 + (lane & 7) + ((lane >> 4) & 1) * 8) * ROWB +
        ((lane >> 3) & 1) * 16;
    float (*stage)[66] = (float (*)[66])(smem + OFF_STG);

    for (int t = 2; t <= 510; t += 2) {
        const __half* hb = g_hist + (size_t)(t - 2) * HB;
        #pragma unroll
        for (int p = 0; p < 4; p++) {
            int f = tid + p * 512;
            int b = f >> 5, c = f & 31;
            if (c < ku2)
                *(uint4*)(smem + OFF_BH + b * ROWB + c * 16) =
                    __ldcg((const uint4*)&hb[(size_t)b * Hn + kbase + c * 8]);
        }
        __syncthreads();

        float acc[2][4][4] = {};
        if (wid < 8) {
            #pragma unroll 5
            for (int kk = 0; kk < ku; kk++) {
                uint32_t A0[4], A1[4], Bv[4], Bw[4];
                ldsm4(A0, aLane + kk * 32);
                ldsm4(A1, aLane + kk * 32 + 16 * ROWB);
                ldsm4(Bv, bLane + kk * 32);
                ldsm4(Bw, bLane + kk * 32 + 16 * ROWB);
                mma16816(acc[0][0], A0, Bv[0], Bv[1]);
                mma16816(acc[0][1], A0, Bv[2], Bv[3]);
                mma16816(acc[0][2], A0, Bw[0], Bw[1]);
                mma16816(acc[0][3], A0, Bw[2], Bw[3]);
                mma16816(acc[1][0], A1, Bv[0], Bv[1]);
                mma16816(acc[1][1], A1, Bv[2], Bv[3]);
                mma16816(acc[1][2], A1, Bw[0], Bw[1]);
                mma16816(acc[1][3], A1, Bw[2], Bw[3]);
            }
            #pragma unroll
            for (int mt = 0; mt < 2; mt++)
                #pragma unroll
                for (int nt = 0; nt < 4; nt++) {
                    int r0 = mt * 16 + g8, cc = nt * 8 + tg * 2;
                    int j = j0 + mg * 32 + r0;
                    int bc = nh * 32 + cc;
                    __stcg((float2*)&g_part[((size_t)kq * Hn + j) * Bn + bc],
                           make_float2(acc[mt][nt][0], acc[mt][nt][1]));
                    __stcg((float2*)&g_part[((size_t)kq * Hn + j + 8) * Bn + bc],
                           make_float2(acc[mt][nt][2], acc[mt][nt][3]));
                }
        }

        float2 vv = make_float2(0.f, 0.f);
        if (cta < 128)
            vv = *(const float2*)&g_V[(size_t)((t >> 1) - 1) * HB + ownIdx];

        grid_sync_dev();

        if (cta < 128) {
            float2 s = vv;
            #pragma unroll
            for (int q = 0; q < KSPLIT; q++) {
                float2 v = __ldcg((const float2*)&g_part[(size_t)q * HB + ownIdx]);
                s.x += v.x; s.y += v.y;
            }
            *(float2*)&stage[jl][bb] = s;
            __syncthreads();
            int b = tid >> 3, kk = tid & 7;
            __half2 hv;
            hv.x = __float2half_rn(stage[kk * 2][b]);
            hv.y = __float2half_rn(stage[kk * 2 + 1][b]);
            *(__half2*)&g_hist[(size_t)t * HB + (size_t)b * Hn + rc + kk * 2] = hv;
        }

        grid_sync_dev();
    }
}

// ---------------------------------------------------------------------------
// out_kernel: even t only. out[b][t][o] = sum_k hist[t][b][k] * woT[o][k]
// ---------------------------------------------------------------------------
__global__ __launch_bounds__(256) void out_kernel(float* __restrict__ out) {
    extern __shared__ char sm[];
    const uint32_t sb = smem_u32(sm);
    const int t = 2 * blockIdx.x, tid = threadIdx.x;
    const int wid = tid >> 5, lane = tid & 31;
    const int mg = wid >> 2, nh = wid & 3;

    const uint32_t aLane = (uint32_t)(mg * 32 + (lane & 15)) * GRB + (lane >> 4) * 16;
    const uint32_t bLane =
        (uint32_t)(nh * 32 + (lane & 7) + ((lane >> 4) & 1) * 8) * GRB +
        ((lane >> 3) & 1) * 16;
    const int g8 = lane >> 2, tg = lane & 3;

    float acc[2][4][4] = {};
    const __half* hsrc = g_hist + (size_t)t * HB;

    for (int k0 = 0; k0 < Hn; k0 += 128) {
        #pragma unroll
        for (int p = 0; p < 4; p++) {
            int f = tid + p * 256;
            int r = f >> 4, c = f & 15;
            *(uint4*)(sm + r * GRB + c * 16) =
                *(const uint4*)&hsrc[(size_t)r * Hn + k0 + c * 8];
        }
        #pragma unroll
        for (int p = 0; p < 8; p++) {
            int f = tid + p * 256;
            int r = f >> 4, c = f & 15;
            *(uint4*)(sm + OFF_OB + r * GRB + c * 16) =
                *(const uint4*)&g_woT[(size_t)r * Hn + k0 + c * 8];
        }
        __syncthreads();
        const uint32_t aB = sb + aLane, bB = sb + OFF_OB + bLane;
        #pragma unroll
        for (int kk = 0; kk < 8; kk++) {
            uint32_t A0[4], A1[4], Bv[4], Bw[4];
            ldsm4(A0, aB + kk * 32);
            ldsm4(A1, aB + kk * 32 + 16 * GRB);
            ldsm4(Bv, bB + kk * 32);
            ldsm4(Bw, bB + kk * 32 + 16 * GRB);
            mma16816(acc[0][0], A0, Bv[0], Bv[1]);
            mma16816(acc[0][1], A0, Bv[2], Bv[3]);
            mma16816(acc[0][2], A0, Bw[0], Bw[1]);
            mma16816(acc[0][3], A0, Bw[2], Bw[3]);
            mma16816(acc[1][0], A1, Bv[0], Bv[1]);
            mma16816(acc[1][1], A1, Bv[2], Bv[3]);
            mma16816(acc[1][2], A1, Bw[0], Bw[1]);
            mma16816(acc[1][3], A1, Bw[2], Bw[3]);
        }
        __syncthreads();
    }

    #pragma unroll
    for (int mt = 0; mt < 2; mt++)
        #pragma unroll
        for (int nt = 0; nt < 4; nt++) {
            int r0 = mt * 16 + g8, cc = nt * 8 + tg * 2;
            int b = mg * 32 + r0;
            int o = nh * 32 + cc;
            *(float2*)&out[((size_t)b * Sn + t) * On + o] =
                make_float2(acc[mt][nt][0], acc[mt][nt][1]);
            *(float2*)&out[((size_t)(b + 8) * Sn + t) * On + o] =
                make_float2(acc[mt][nt][2], acc[mt][nt][3]);
        }
}

// ---------------------------------------------------------------------------
// oddout_kernel: odd t. out = h_{t-1}@Wm(hi+lo) + (0.005 n)@woT + x@Wxo(hi+lo)
// one CTA per odd t (grid 256), 256 thr / 8 warps.
// ---------------------------------------------------------------------------
__global__ __launch_bounds__(256) void oddout_kernel(const float* __restrict__ noise,
                                                     float* __restrict__ out) {
    extern __shared__ char sm[];
    const uint32_t sb = smem_u32(sm);
    const int t = 2 * blockIdx.x + 1, tid = threadIdx.x;
    const int wid = tid >> 5, lane = tid & 31;
    const int mg = wid >> 2, nh = wid & 3;
    const int g8 = lane >> 2, tg = lane & 3;

    const uint32_t aOff = (uint32_t)(mg * 32 + (lane & 15)) * GRB + (lane >> 4) * 16;
    const uint32_t bOff =
        (uint32_t)(nh * 32 + (lane & 7) + ((lane >> 4) & 1) * 8) * GRB +
        ((lane >> 3) & 1) * 16;

    float a1[2][4][4] = {}, a2[2][4][4] = {};
    const __half* hsrc = g_hist + (size_t)(t - 1) * HB;

    for (int k0 = 0; k0 < Hn; k0 += 128) {
        // A_h: h_{t-1} fp16
        #pragma unroll
        for (int p = 0; p < 4; p++) {
            int f = tid + p * 256;
            int r = f >> 4, c = f & 15;
            *(uint4*)(sm + OO_AH + r * GRB + c * 16) =
                *(const uint4*)&hsrc[(size_t)r * Hn + k0 + c * 8];
        }
        // A_n: 0.005 * noise, fp32 -> fp16
        #pragma unroll
        for (int p = 0; p < 8; p++) {
            int f = tid + p * 256;                 // 2048 groups of 4 floats
            int r = f >> 5, c4 = f & 31;
            float4 v = *(const float4*)&noise[((size_t)r * Sn + (t - 1)) * Hn +
                                              k0 + c4 * 4];
            char* dst = sm + OO_AN + r * GRB + c4 * 8;
            *(__half2*)dst = __floats2half2_rn(kNoise * v.x, kNoise * v.y);
            *(__half2*)(dst + 4) = __floats2half2_rn(kNoise * v.z, kNoise * v.w);
        }
        // B tiles
        #pragma unroll
        for (int p = 0; p < 8; p++) {
            int f = tid + p * 256;
            int r = f >> 4, c = f & 15;
            size_t gi = (size_t)r * Hn + k0 + c * 8;
            *(uint4*)(sm + OO_WMH + r * GRB + c * 16) = *(const uint4*)&g_WmTh[gi];
            *(uint4*)(sm + OO_WML + r * GRB + c * 16) = *(const uint4*)&g_WmTl[gi];
            *(uint4*)(sm + OO_WO + r * GRB + c * 16) = *(const uint4*)&g_woT[gi];
        }
        __syncthreads();
        #pragma unroll
        for (int kk = 0; kk < 8; kk++) {
            uint32_t A0[4], A1[4], Bv[4], Bw[4];
            ldsm4(A0, sb + OO_AH + aOff + kk * 32);
            ldsm4(A1, sb + OO_AH + aOff + kk * 32 + 16 * GRB);
            ldsm4(Bv, sb + OO_WMH + bOff + kk * 32);
            ldsm4(Bw, sb + OO_WMH + bOff + kk * 32 + 16 * GRB);
            mma16816(a1[0][0], A0, Bv[0], Bv[1]); mma16816(a1[0][1], A0, Bv[2], Bv[3]);
            mma16816(a1[0][2], A0, Bw[0], Bw[1]); mma16816(a1[0][3], A0, Bw[2], Bw[3]);
            mma16816(a1[1][0], A1, Bv[0], Bv[1]); mma16816(a1[1][1], A1, Bv[2], Bv[3]);
            mma16816(a1[1][2], A1, Bw[0], Bw[1]); mma16816(a1[1][3], A1, Bw[2], Bw[3]);
            ldsm4(Bv, sb + OO_WML + bOff + kk * 32);
            ldsm4(Bw, sb + OO_WML + bOff + kk * 32 + 16 * GRB);
            mma16816(a2[0][0], A0, Bv[0], Bv[1]); mma16816(a2[0][1], A0, Bv[2], Bv[3]);
            mma16816(a2[0][2], A0, Bw[0], Bw[1]); mma16816(a2[0][3], A0, Bw[2], Bw[3]);
            mma16816(a2[1][0], A1, Bv[0], Bv[1]); mma16816(a2[1][1], A1, Bv[2], Bv[3]);
            mma16816(a2[1][2], A1, Bw[0], Bw[1]); mma16816(a2[1][3], A1, Bw[2], Bw[3]);
            ldsm4(A0, sb + OO_AN + aOff + kk * 32);
            ldsm4(A1, sb + OO_AN + aOff + kk * 32 + 16 * GRB);
            ldsm4(Bv, sb + OO_WO + bOff + kk * 32);
            ldsm4(Bw, sb + OO_WO + bOff + kk * 32 + 16 * GRB);
            mma16816(a1[0][0], A0, Bv[0], Bv[1]); mma16816(a1[0][1], A0, Bv[2], Bv[3]);
            mma16816(a1[0][2], A0, Bw[0], Bw[1]); mma16816(a1[0][3], A0, Bw[2], Bw[3]);
            mma16816(a1[1][0], A1, Bv[0], Bv[1]); mma16816(a1[1][1], A1, Bv[2], Bv[3]);
            mma16816(a1[1][2], A1, Bw[0], Bw[1]); mma16816(a1[1][3], A1, Bw[2], Bw[3]);
        }
        __syncthreads();
    }

    // x-term: one K=128 chunk. A = g_xh, B = WxoT hi/lo.
    #pragma unroll
    for (int p = 0; p < 4; p++) {
        int f = tid + p * 256;
        int r = f >> 4, c = f & 15;
        *(uint4*)(sm + OO_AH + r * GRB + c * 16) =
            *(const uint4*)&g_xh[((size_t)r * Sn + (t - 1)) * In + c * 8];
    }
    #pragma unroll
    for (int p = 0; p < 8; p++) {
        int f = tid + p * 256;
        int r = f >> 4, c = f & 15;
        size_t gi = (size_t)r * In + c * 8;
        *(uint4*)(sm + OO_WMH + r * GRB + c * 16) = *(const uint4*)&g_WxoTh[gi];
        *(uint4*)(sm + OO_WML + r * GRB + c * 16) = *(const uint4*)&g_WxoTl[gi];
    }
    __syncthreads();
    #pragma unroll
    for (int kk = 0; kk < 8; kk++) {
        uint32_t A0[4], A1[4], Bv[4], Bw[4];
        ldsm4(A0, sb + OO_AH + aOff + kk * 32);
        ldsm4(A1, sb + OO_AH + aOff + kk * 32 + 16 * GRB);
        ldsm4(Bv, sb + OO_WMH + bOff + kk * 32);
        ldsm4(Bw, sb + OO_WMH + bOff + kk * 32 + 16 * GRB);
        mma16816(a1[0][0], A0, Bv[0], Bv[1]); mma16816(a1[0][1], A0, Bv[2], Bv[3]);
        mma16816(a1[0][2], A0, Bw[0], Bw[1]); mma16816(a1[0][3], A0, Bw[2], Bw[3]);
        mma16816(a1[1][0], A1, Bv[0], Bv[1]); mma16816(a1[1][1], A1, Bv[2], Bv[3]);
        mma16816(a1[1][2], A1, Bw[0], Bw[1]); mma16816(a1[1][3], A1, Bw[2], Bw[3]);
        ldsm4(Bv, sb + OO_WML + bOff + kk * 32);
        ldsm4(Bw, sb + OO_WML + bOff + kk * 32 + 16 * GRB);
        mma16816(a2[0][0], A0, Bv[0], Bv[1]); mma16816(a2[0][1], A0, Bv[2], Bv[3]);
        mma16816(a2[0][2], A0, Bw[0], Bw[1]); mma16816(a2[0][3], A0, Bw[2], Bw[3]);
        mma16816(a2[1][0], A1, Bv[0], Bv[1]); mma16816(a2[1][1], A1, Bv[2], Bv[3]);
        mma16816(a2[1][2], A1, Bw[0], Bw[1]); mma16816(a2[1][3], A1, Bw[2], Bw[3]);
    }

    #pragma unroll
    for (int mt = 0; mt < 2; mt++)
        #pragma unroll
        for (int nt = 0; nt < 4; nt++) {
            int r0 = mt * 16 + g8, cc = nt * 8 + tg * 2;
            int b = mg * 32 + r0;
            int o = nh * 32 + cc;
            *(float2*)&out[((size_t)b * Sn + t) * On + o] =
                make_float2(fmaf(kLoInv, a2[mt][nt][0], a1[mt][nt][0]),
                            fmaf(kLoInv, a2[mt][nt][1], a1[mt][nt][1]));
            *(float2*)&out[((size_t)(b + 8) * Sn + t) * On + o] =
                make_float2(fmaf(kLoInv, a2[mt][nt][2], a1[mt][nt][2]),
                            fmaf(kLoInv, a2[mt][nt][3], a1[mt][nt][3]));
        }
}

// ---------------------------------------------------------------------------
extern "C" void kernel_launch(void* const* d_in, const int* in_sizes, int n_in,
                              void* d_out, int out_size) {
    const float* x     = (const float*)d_in[0];
    const float* noise = (const float*)d_in[1];
    const float* wi    = (const float*)d_in[2];
    const float* wrec  = (const float*)d_in[3];
    const float* wout  = (const float*)d_in[4];
    const float* g     = (const float*)d_in[5];
    const float* h0    = (const float*)d_in[6];
    float* out = (float*)d_out;

    cudaFuncSetAttribute(loop_kernel, cudaFuncAttributeMaxDynamicSharedMemorySize,
                         SMEM_TOTAL);
    cudaFuncSetAttribute(u_kernel, cudaFuncAttributeMaxDynamicSharedMemorySize, USMEM);
    cudaFuncSetAttribute(out_kernel, cudaFuncAttributeMaxDynamicSharedMemorySize, OSMEM);
    cudaFuncSetAttribute(mm2_kernel, cudaFuncAttributeMaxDynamicSharedMemorySize,
                         MM2_SMEM);
    cudaFuncSetAttribute(wmprep_kernel, cudaFuncAttributeMaxDynamicSharedMemorySize,
                         MM2_SMEM);
    cudaFuncSetAttribute(v_kernel, cudaFuncAttributeMaxDynamicSharedMemorySize, V2_SMEM);
    cudaFuncSetAttribute(oddout_kernel, cudaFuncAttributeMaxDynamicSharedMemorySize,
                         OODD_SMEM);

    mprep_kernel<<<dim3(Hn / 32, Hn / 32), dim3(32, 32)>>>(wrec, g);
    wtprep_kernel<<<dim3(Hn / 32, On / 32), dim3(32, 32)>>>(wout);
    witprep_kernel<<<dim3(In / 32, Hn / 32), dim3(32, 32)>>>(wi);
    wxoprep_kernel<<<In, On>>>(wi, wout);
    xhprep_kernel<<<Bn * Sn * In / 256, 256>>>(x);
    hbinit_kernel<<<HB / 256, 256>>>(h0);
    u_kernel<<<dim3(Hn / 128, 128), 256, USMEM>>>(noise);
    mm2_kernel<<<dim3(16, 16), 512, MM2_SMEM>>>();
    wmprep_kernel<<<16, 512, MM2_SMEM>>>();
    v_kernel<<<dim3(16, 64), 512, V2_SMEM>>>();
    loop_kernel<<<NCTA, NTHR, SMEM_TOTAL>>>();
    out_kernel<<<256, 256, OSMEM>>>(out);
    oddout_kernel<<<256, 256, OODD_SMEM>>>(noise, out);
}